// round 15
// baseline (speedup 1.0000x reference)
#include <cuda_runtime.h>
#include <cuda_bf16.h>
#include <cuda_fp16.h>
#include <math.h>
#include <stdint.h>

// ---------------------------------------------------------------------------
// DecoderWithAttention: B=64, E=512, H=W=16, T=16, D=512, A=512, V=5000
// Mixed-precision mma.sync pipeline (R14 config, leaner graph):
//  - LSTM recurrence (Whh, h-state): bf16 hi/lo 3-pass (proven)
//  - Xp projections + attention + fc: fp16 hi/lo 2-pass (B hi-only), BK=32
//  - fc distributed with fused gate combine; gate fused into awe kernel
//  - 19 kernel launches; layer-1 packs on side stream behind evPk1
// ---------------------------------------------------------------------------

#define B_ 64
#define E_ 512
#define T_ 16
#define D_ 512
#define P_ 256
#define A_ 512
#define V_ 5000

// ------------------------------ scratch ------------------------------------
__device__ float g_fh    [B_ * P_ * E_];
__device__ float g_XpAll1[T_ * B_ * 8 * D_];
__device__ float g_XpAll2[T_ * B_ * 8 * D_];
__device__ float g_hidden[T_ * B_ * 2 * D_];
__device__ float g_att1  [B_ * P_ * A_];
__device__ float g_att2  [T_ * B_ * A_];
__device__ float g_alpha [T_ * B_ * P_];
__device__ float g_bAll1 [8 * D_];
__device__ float g_bAll2 [8 * D_];
__device__ float g_fcH   [T_ * B_ * V_];
__device__ float g_gate  [T_ * B_ * 2];

// A-operand hi/lo planes (uint32 = 2 packed halves; lo plane at +M*K/2)
__device__ uint32_t g_featsP[2 * 1024 * 256];   // fp16 (Xp1)
__device__ uint32_t g_fhP  [2 * 16384 * 256];   // fp16 (att1)
__device__ uint32_t g_x2P  [2 * 1024 * 512];    // fp16 (Xp2)
__device__ uint32_t g_hidP [2 * 1024 * 512];    // fp16 (att2 + fcH)
__device__ uint32_t g_aweP [2 * 1024 * 256];    // fp16 (fcA)
__device__ uint32_t g_hstate[4 * 128 * 256];    // bf16 recurrence state

// bf16 fragment-packed weights (recurrence): [n8][k16][lane] uint4
__device__ uint4 g_Whh1p [2 * (2048/8) * (512/16) * 32];   // fwd | rev
__device__ uint4 g_Whh2p [2 * (2048/8) * (512/16) * 32];
// fp16 hi-only packed weights: [n8][k16][lane] uint2 {h0,h1}
__device__ uint2 g_WihAll1p[(4096/8) * (512/16)  * 32];
__device__ uint2 g_WihAll2p[(4096/8) * (1024/16) * 32];
__device__ uint2 g_Wencp [(512/8)  * (512/16) * 32];
__device__ uint2 g_Wdecp [(512/8)  * (1024/16)* 32];
__device__ uint2 g_WfcHp [(5000/8) * (1024/16)* 32];
__device__ uint2 g_WfcAp [(5000/8) * (512/16) * 32];

__device__ int g_bar_cnt = 0;
__device__ volatile int g_bar_sense = 0;

// ------------------------------ helpers ------------------------------------
__device__ __forceinline__ void mma_bf16(float* d, const uint32_t* a, const uint32_t* b) {
    asm volatile(
        "mma.sync.aligned.m16n8k16.row.col.f32.bf16.bf16.f32 "
        "{%0,%1,%2,%3}, {%4,%5,%6,%7}, {%8,%9}, {%0,%1,%2,%3};\n"
        : "+f"(d[0]), "+f"(d[1]), "+f"(d[2]), "+f"(d[3])
        : "r"(a[0]), "r"(a[1]), "r"(a[2]), "r"(a[3]), "r"(b[0]), "r"(b[1]));
}
__device__ __forceinline__ void mma_f16(float* d, const uint32_t* a, const uint32_t* b) {
    asm volatile(
        "mma.sync.aligned.m16n8k16.row.col.f32.f16.f16.f32 "
        "{%0,%1,%2,%3}, {%4,%5,%6,%7}, {%8,%9}, {%0,%1,%2,%3};\n"
        : "+f"(d[0]), "+f"(d[1]), "+f"(d[2]), "+f"(d[3])
        : "r"(a[0]), "r"(a[1]), "r"(a[2]), "r"(a[3]), "r"(b[0]), "r"(b[1]));
}

__device__ __forceinline__ void split2(float x0, float x1, uint32_t& hi, uint32_t& lo) {
    __nv_bfloat16 h0 = __float2bfloat16_rn(x0);
    __nv_bfloat16 h1 = __float2bfloat16_rn(x1);
    __nv_bfloat162 hp = __halves2bfloat162(h0, h1);
    hi = *(uint32_t*)&hp;
    __nv_bfloat162 lp = __floats2bfloat162_rn(x0 - __bfloat162float(h0),
                                              x1 - __bfloat162float(h1));
    lo = *(uint32_t*)&lp;
}
__device__ __forceinline__ void split2h(float x0, float x1, uint32_t& hi, uint32_t& lo) {
    __half h0 = __float2half_rn(x0);
    __half h1 = __float2half_rn(x1);
    __half2 hp = __halves2half2(h0, h1);
    hi = *(uint32_t*)&hp;
    __half2 lp = __floats2half2_rn(x0 - __half2float(h0), x1 - __half2float(h1));
    lo = *(uint32_t*)&lp;
}

// bf16 hi/lo fragment pack for a fwd/rev pair (one launch)
__global__ void pack_w2(const float* __restrict__ W0, const float* __restrict__ W1,
                        uint4* __restrict__ Wp, int N, int K, int halfOff) {
    int idx = blockIdx.x * 256 + threadIdx.x;
    int K16 = K >> 4;
    int total = (N >> 3) * K16 * 32;
    if (idx >= 2 * total) return;
    const float* W = (idx < total) ? W0 : W1;
    uint4* dst = Wp + ((idx < total) ? 0 : halfOff);
    int id = (idx < total) ? idx : idx - total;
    int lane = id & 31;
    int k16 = (id >> 5) % K16;
    int n8 = id / (32 * K16);
    int g = lane >> 2, tq = lane & 3;
    const float* src = W + (size_t)(n8 * 8 + g) * K + k16 * 16;
    uint4 o;
    split2(src[2 * tq],     src[2 * tq + 1], o.x, o.z);
    split2(src[2 * tq + 8], src[2 * tq + 9], o.y, o.w);
    dst[id] = o;
}

// fp16 hi-only fragment pack with source row-stride/column-offset
__global__ void pack_wh(const float* __restrict__ W, uint2* __restrict__ Wp,
                        int N, int K, int srcStride, int colOff) {
    int idx = blockIdx.x * 256 + threadIdx.x;
    int K16 = K >> 4;
    int total = (N >> 3) * K16 * 32;
    if (idx >= total) return;
    int lane = idx & 31;
    int k16 = (idx >> 5) % K16;
    int n8 = idx / (32 * K16);
    int g = lane >> 2, tq = lane & 3;
    const float* src = W + (size_t)(n8 * 8 + g) * srcStride + colOff + k16 * 16;
    __half2 a = __floats2half2_rn(src[2 * tq],     src[2 * tq + 1]);
    __half2 b = __floats2half2_rn(src[2 * tq + 8], src[2 * tq + 9]);
    Wp[idx] = make_uint2(*(uint32_t*)&a, *(uint32_t*)&b);
}

// fp16 hi-only pack for a fwd/rev pair
__global__ void pack_wh2(const float* __restrict__ W0, const float* __restrict__ W1,
                         uint2* __restrict__ Wp, int N, int K, int halfOff) {
    int idx = blockIdx.x * 256 + threadIdx.x;
    int K16 = K >> 4;
    int total = (N >> 3) * K16 * 32;
    if (idx >= 2 * total) return;
    const float* W = (idx < total) ? W0 : W1;
    uint2* dst = Wp + ((idx < total) ? 0 : halfOff);
    int id = (idx < total) ? idx : idx - total;
    int lane = id & 31;
    int k16 = (id >> 5) % K16;
    int n8 = id / (32 * K16);
    int g = lane >> 2, tq = lane & 3;
    const float* src = W + (size_t)(n8 * 8 + g) * K + k16 * 16;
    __half2 a = __floats2half2_rn(src[2 * tq],     src[2 * tq + 1]);
    __half2 b = __floats2half2_rn(src[2 * tq + 8], src[2 * tq + 9]);
    dst[id] = make_uint2(*(uint32_t*)&a, *(uint32_t*)&b);
}

// both layers' combined biases in one launch (grid 32)
__global__ void bias_all(const float* __restrict__ a1, const float* __restrict__ a2,
                         const float* __restrict__ a3, const float* __restrict__ a4,
                         const float* __restrict__ c1, const float* __restrict__ c2,
                         const float* __restrict__ c3, const float* __restrict__ c4,
                         float* __restrict__ o1, float* __restrict__ o2) {
    int i = blockIdx.x * 256 + threadIdx.x;
    int j = i & 4095;
    if (i < 4096)
        o1[j] = (j < 4 * D_ / 2 * 2 && j < 2048) ? (a1[j] + a2[j]) : (a3[j - 2048] + a4[j - 2048]);
    else
        o2[j] = (j < 2048) ? (c1[j] + c2[j]) : (c3[j - 2048] + c4[j - 2048]);
}

// fh[b][p][e] = enc[b][e][p]; emits fp32 fh + fp16 hi/lo planes
__global__ void transpose_fh_kernel(const float* __restrict__ enc, float* __restrict__ fh,
                                    uint32_t* __restrict__ fhP) {
    __shared__ float tile[32][33];
    const size_t FH_LO = (size_t)16384 * 256;
    int b  = blockIdx.z;
    int e0 = blockIdx.x * 32;
    int p0 = blockIdx.y * 32;
    int x = threadIdx.x;
#pragma unroll
    for (int i = 0; i < 4; i++) {
        int y = threadIdx.y + i * 8;
        tile[y][x] = enc[((size_t)b * E_ + e0 + y) * P_ + p0 + x];
    }
    __syncthreads();
    int it = threadIdx.y * 32 + threadIdx.x;
#pragma unroll
    for (int i = 0; i < 2; i++) {
        int item = it + i * 256;
        int yy = item >> 4;
        int xx = item & 15;
        float v0 = tile[2 * xx][yy];
        float v1 = tile[2 * xx + 1][yy];
        size_t row = (size_t)b * P_ + p0 + yy;
        fh[row * E_ + e0 + 2 * xx]     = v0;
        fh[row * E_ + e0 + 2 * xx + 1] = v1;
        uint32_t hw, lw;
        split2h(v0, v1, hw, lw);
        size_t w = row * 256 + (e0 >> 1) + xx;
        fhP[w] = hw;
        fhP[FH_LO + w] = lw;
    }
}

// feats fp16 planes
__global__ void feats_kernel(const float* __restrict__ enc, uint32_t* __restrict__ featsP) {
    const size_t F_LO = (size_t)1024 * 256;
    int gi = blockIdx.x * blockDim.x + threadIdx.x;
    if (gi >= T_ * B_ * 256) return;
    int t = gi & 15;
    int e2 = (gi >> 4) & 255;
    int b = gi >> 12;
    const float* s0 = enc + ((size_t)b * E_ + 2 * e2) * P_ + t;
    const float* s1 = s0 + P_;
    float a0 = 0.f, a1 = 0.f;
#pragma unroll
    for (int h = 0; h < 16; h++) { a0 += s0[h * 16]; a1 += s1[h * 16]; }
    uint32_t hw, lw;
    split2h(a0 * (1.f / 16.f), a1 * (1.f / 16.f), hw, lw);
    size_t w = ((size_t)t * B_ + b) * 256 + e2;
    featsP[w] = hw;
    featsP[F_LO + w] = lw;
}

#define ASW 12
#define ASW2 20

// ---------------------- fp16x2 GEMM (2-pass, BK=32) --------------------------
__global__ __launch_bounds__(256, 2) void gemm_f16x2(
    const uint32_t* __restrict__ Ap, const uint2* __restrict__ Wp,
    const float* __restrict__ b1,
    float* __restrict__ C, int M, int N, int K)
{
    __shared__ __align__(16) uint32_t Ah[2][128][ASW2];
    __shared__ __align__(16) uint32_t Al[2][128][ASW2];

    int tid  = threadIdx.x;
    int wid  = tid >> 5, lane = tid & 31;
    int g = lane >> 2, tq = lane & 3;
    int m0 = blockIdx.y * 128, n0 = blockIdx.x * 64;
    int wm = wid * 16;
    int K2 = K >> 1, K16 = K >> 4, K32 = K >> 5;
    int nTiles = N >> 3;
    size_t loOff = (size_t)M * K2;

    const uint2* bp[8];
    bool bok[8];
#pragma unroll
    for (int j = 0; j < 8; j++) {
        int n8 = (n0 >> 3) + j;
        bok[j] = (n8 < nTiles);
        bp[j] = Wp + ((size_t)(bok[j] ? n8 : 0) * K16) * 32 + lane;
    }

    float acc[8][4];
#pragma unroll
    for (int j = 0; j < 8; j++)
#pragma unroll
        for (int v = 0; v < 4; v++) acc[j][v] = 0.f;

    int r = tid >> 1, seg = tid & 1;
    const uint4* aH = (const uint4*)(Ap + (size_t)(m0 + r) * K2) + 2 * seg;
    const uint4* aL = (const uint4*)(Ap + loOff + (size_t)(m0 + r) * K2) + 2 * seg;

    // preload chunk 0 (32 k)
    {
        uint4 h0 = aH[0], h1 = aH[1];
        uint4 l0 = aL[0], l1 = aL[1];
        *(uint4*)&Ah[0][r][seg * 8]     = h0;
        *(uint4*)&Ah[0][r][seg * 8 + 4] = h1;
        *(uint4*)&Al[0][r][seg * 8]     = l0;
        *(uint4*)&Al[0][r][seg * 8 + 4] = l1;
    }
    __syncthreads();

    int buf = 0;
    for (int kc = 0; kc < K32; kc++) {
        bool more = (kc + 1) < K32;
        uint4 nh0, nh1, nl0, nl1;
        if (more) {
            nh0 = aH[(kc + 1) * 4];
            nh1 = aH[(kc + 1) * 4 + 1];
            nl0 = aL[(kc + 1) * 4];
            nl1 = aL[(kc + 1) * 4 + 1];
        }
#pragma unroll
        for (int ktl = 0; ktl < 2; ktl++) {
            int kt = kc * 2 + ktl;
            uint32_t ah[4], al[4];
            {
                int rA = wm + g, rB = rA + 8;
                int cb = ktl * 8 + tq;
                ah[0] = Ah[buf][rA][cb];     ah[1] = Ah[buf][rB][cb];
                ah[2] = Ah[buf][rA][cb + 4]; ah[3] = Ah[buf][rB][cb + 4];
                al[0] = Al[buf][rA][cb];     al[1] = Al[buf][rB][cb];
                al[2] = Al[buf][rA][cb + 4]; al[3] = Al[buf][rB][cb + 4];
            }
#pragma unroll
            for (int j = 0; j < 8; j++) {
                uint2 bv = bok[j] ? bp[j][kt * 32] : make_uint2(0u, 0u);
                uint32_t bh[2] = {bv.x, bv.y};
                mma_f16(acc[j], ah, bh);
                mma_f16(acc[j], al, bh);
            }
        }
        if (more) {
            *(uint4*)&Ah[buf ^ 1][r][seg * 8]     = nh0;
            *(uint4*)&Ah[buf ^ 1][r][seg * 8 + 4] = nh1;
            *(uint4*)&Al[buf ^ 1][r][seg * 8]     = nl0;
            *(uint4*)&Al[buf ^ 1][r][seg * 8 + 4] = nl1;
            __syncthreads();
            buf ^= 1;
        }
    }

#pragma unroll
    for (int j = 0; j < 8; j++) {
        int rr = m0 + wm + g;
        int c0 = n0 + j * 8 + 2 * tq;
#pragma unroll
        for (int cc = 0; cc < 2; cc++) {
            int c = c0 + cc;
            if (c < N) {
                float bias = b1 ? b1[c] : 0.f;
                C[(size_t)rr * N + c]       = acc[j][cc]     + bias;
                C[(size_t)(rr + 8) * N + c] = acc[j][2 + cc] + bias;
            }
        }
    }
}

// ------------- fp16x2 GEMM (BK=32) with fused gate-combine epilogue ----------
__global__ __launch_bounds__(256, 2) void gemm_f16x2_fc(
    const uint32_t* __restrict__ Ap, const uint2* __restrict__ Wp,
    const float* __restrict__ fcH, const float* __restrict__ gate,
    const float* __restrict__ bfc,
    float* __restrict__ C, int M, int N, int K)
{
    __shared__ __align__(16) uint32_t Ah[2][128][ASW2];
    __shared__ __align__(16) uint32_t Al[2][128][ASW2];

    int tid  = threadIdx.x;
    int wid  = tid >> 5, lane = tid & 31;
    int g = lane >> 2, tq = lane & 3;
    int m0 = blockIdx.y * 128, n0 = blockIdx.x * 64;
    int wm = wid * 16;
    int K2 = K >> 1, K16 = K >> 4, K32 = K >> 5;
    int nTiles = N >> 3;
    size_t loOff = (size_t)M * K2;

    const uint2* bp[8];
    bool bok[8];
#pragma unroll
    for (int j = 0; j < 8; j++) {
        int n8 = (n0 >> 3) + j;
        bok[j] = (n8 < nTiles);
        bp[j] = Wp + ((size_t)(bok[j] ? n8 : 0) * K16) * 32 + lane;
    }

    float acc[8][4];
#pragma unroll
    for (int j = 0; j < 8; j++)
#pragma unroll
        for (int v = 0; v < 4; v++) acc[j][v] = 0.f;

    int r = tid >> 1, seg = tid & 1;
    const uint4* aH = (const uint4*)(Ap + (size_t)(m0 + r) * K2) + 2 * seg;
    const uint4* aL = (const uint4*)(Ap + loOff + (size_t)(m0 + r) * K2) + 2 * seg;

    {
        uint4 h0 = aH[0], h1 = aH[1];
        uint4 l0 = aL[0], l1 = aL[1];
        *(uint4*)&Ah[0][r][seg * 8]     = h0;
        *(uint4*)&Ah[0][r][seg * 8 + 4] = h1;
        *(uint4*)&Al[0][r][seg * 8]     = l0;
        *(uint4*)&Al[0][r][seg * 8 + 4] = l1;
    }
    __syncthreads();

    int buf = 0;
    for (int kc = 0; kc < K32; kc++) {
        bool more = (kc + 1) < K32;
        uint4 nh0, nh1, nl0, nl1;
        if (more) {
            nh0 = aH[(kc + 1) * 4];
            nh1 = aH[(kc + 1) * 4 + 1];
            nl0 = aL[(kc + 1) * 4];
            nl1 = aL[(kc + 1) * 4 + 1];
        }
#pragma unroll
        for (int ktl = 0; ktl < 2; ktl++) {
            int kt = kc * 2 + ktl;
            uint32_t ah[4], al[4];
            {
                int rA = wm + g, rB = rA + 8;
                int cb = ktl * 8 + tq;
                ah[0] = Ah[buf][rA][cb];     ah[1] = Ah[buf][rB][cb];
                ah[2] = Ah[buf][rA][cb + 4]; ah[3] = Ah[buf][rB][cb + 4];
                al[0] = Al[buf][rA][cb];     al[1] = Al[buf][rB][cb];
                al[2] = Al[buf][rA][cb + 4]; al[3] = Al[buf][rB][cb + 4];
            }
#pragma unroll
            for (int j = 0; j < 8; j++) {
                uint2 bv = bok[j] ? bp[j][kt * 32] : make_uint2(0u, 0u);
                uint32_t bh[2] = {bv.x, bv.y};
                mma_f16(acc[j], ah, bh);
                mma_f16(acc[j], al, bh);
            }
        }
        if (more) {
            *(uint4*)&Ah[buf ^ 1][r][seg * 8]     = nh0;
            *(uint4*)&Ah[buf ^ 1][r][seg * 8 + 4] = nh1;
            *(uint4*)&Al[buf ^ 1][r][seg * 8]     = nl0;
            *(uint4*)&Al[buf ^ 1][r][seg * 8 + 4] = nl1;
            __syncthreads();
            buf ^= 1;
        }
    }

    int rr0 = m0 + wm + g;
    float g0a = gate[(size_t)rr0 * 2],       g1a = gate[(size_t)rr0 * 2 + 1];
    float g0b = gate[(size_t)(rr0 + 8) * 2], g1b = gate[(size_t)(rr0 + 8) * 2 + 1];
#pragma unroll
    for (int j = 0; j < 8; j++) {
        int c0 = n0 + j * 8 + 2 * tq;
#pragma unroll
        for (int cc = 0; cc < 2; cc++) {
            int c = c0 + cc;
            if (c < N) {
                float bias = bfc[c];
                size_t ia = (size_t)rr0 * N + c;
                size_t ib = (size_t)(rr0 + 8) * N + c;
                C[ia] = g0a * fcH[ia] + g1a * acc[j][cc]     + bias;
                C[ib] = g0b * fcH[ib] + g1b * acc[j][2 + cc] + bias;
            }
        }
    }
}

// ---------------------- persistent LSTM (split-K, bf16 3-pass) ---------------
__device__ __forceinline__ void grid_barrier(int step) {
    __threadfence();
    __syncthreads();
    if (threadIdx.x == 0) {
        int target = (step + 1) & 1;
        if (atomicAdd(&g_bar_cnt, 1) == (int)gridDim.x - 1) {
            atomicExch(&g_bar_cnt, 0);
            __threadfence();
            g_bar_sense = target;
        } else {
            while (g_bar_sense != target) __nanosleep(32);
        }
        __threadfence();
    }
    __syncthreads();
}

// 128 blocks x 256 threads. dir = bid>>6, d-slice = bid&63 (8 d each).
__global__ __launch_bounds__(256) void lstm_persist(
    const float* __restrict__ XpAll,
    const uint4* __restrict__ Whp2,       // fwd | rev halves
    uint32_t* __restrict__ hstate,
    uint32_t* __restrict__ outP, float* __restrict__ outF32, int whHalfOff)
{
    __shared__ __align__(16) uint32_t Hh[2][128][ASW];
    __shared__ __align__(16) uint32_t Hl[2][128][ASW];
    __shared__ float red[4][32][16];

    const int HS = 128 * 256;
    const size_t OUT_LO = (size_t)1024 * 512;

    int tid = threadIdx.x;
    int w = tid >> 5, lane = tid & 31;
    int g = lane >> 2, tq = lane & 3;
    int dir = blockIdx.x >> 6;
    int idx = blockIdx.x & 63;
    int d0 = idx * 8;
    const uint4* Whp = Whp2 + (dir ? whHalfOff : 0);
    const int K16tot = D_ >> 4;   // 32
    int kg = w >> 2;
    int wl = w & 3;

    const uint4* bp[4];
#pragma unroll
    for (int j = 0; j < 4; j++)
        bp[j] = Whp + ((size_t)(j * 64 + idx) * K16tot) * 32 + lane;

    int sKg = tid >> 7;
    int sR  = (tid >> 1) & 63;
    int sKh = tid & 1;

    float creg[4] = {0.f, 0.f, 0.f, 0.f};

    for (int t = 0; t < T_; t++) {
        float acc[4][4];
#pragma unroll
        for (int j = 0; j < 4; j++)
#pragma unroll
            for (int v = 0; v < 4; v++) acc[j][v] = 0.f;

        if (t > 0) {
            int ib = (t - 1) & 1;
            const uint32_t* hHi = hstate + (size_t)(2 * ib) * HS;
            const uint32_t* hLo = hHi + HS;
            const uint4* sH = (const uint4*)(hHi + (size_t)(dir * 64 + sR) * 256) + sKg * 32 + sKh;
            const uint4* sL = (const uint4*)(hLo + (size_t)(dir * 64 + sR) * 256) + sKg * 32 + sKh;

            {
                uint4 h = sH[0], l = sL[0];
                *(uint4*)&Hh[0][sKg * 64 + sR][sKh * 4] = h;
                *(uint4*)&Hl[0][sKg * 64 + sR][sKh * 4] = l;
            }
            uint4 breg[4];
#pragma unroll
            for (int j = 0; j < 4; j++) breg[j] = bp[j][(kg * 16) * 32];
            __syncthreads();

            int buf = 0;
            for (int kt = 0; kt < 16; kt++) {
                bool more = (kt + 1) < 16;
                uint4 nh, nl, bnext[4];
                if (more) {
                    nh = sH[(kt + 1) * 2];
                    nl = sL[(kt + 1) * 2];
#pragma unroll
                    for (int j = 0; j < 4; j++) bnext[j] = bp[j][(kg * 16 + kt + 1) * 32];
                }
                int rA = kg * 64 + wl * 16 + g, rB = rA + 8;
                uint32_t ah[4], al[4];
                ah[0] = Hh[buf][rA][tq];     ah[1] = Hh[buf][rB][tq];
                ah[2] = Hh[buf][rA][tq + 4]; ah[3] = Hh[buf][rB][tq + 4];
                al[0] = Hl[buf][rA][tq];     al[1] = Hl[buf][rB][tq];
                al[2] = Hl[buf][rA][tq + 4]; al[3] = Hl[buf][rB][tq + 4];
#pragma unroll
                for (int j = 0; j < 4; j++) {
                    uint32_t bh[2] = {breg[j].x, breg[j].y};
                    uint32_t bl[2] = {breg[j].z, breg[j].w};
                    mma_bf16(acc[j], ah, bh);
                    mma_bf16(acc[j], al, bh);
                    mma_bf16(acc[j], ah, bl);
                }
                if (more) {
                    *(uint4*)&Hh[buf ^ 1][sKg * 64 + sR][sKh * 4] = nh;
                    *(uint4*)&Hl[buf ^ 1][sKg * 64 + sR][sKh * 4] = nl;
                    __syncthreads();
                    buf ^= 1;
#pragma unroll
                    for (int j = 0; j < 4; j++) breg[j] = bnext[j];
                }
            }
            if (w >= 4) {
#pragma unroll
                for (int j = 0; j < 4; j++)
#pragma unroll
                    for (int v = 0; v < 4; v++) red[wl][lane][j * 4 + v] = acc[j][v];
            }
            __syncthreads();
            if (w < 4) {
#pragma unroll
                for (int j = 0; j < 4; j++)
#pragma unroll
                    for (int v = 0; v < 4; v++) acc[j][v] += red[w][lane][j * 4 + v];
            }
        }

        if (w < 4) {
            int ob = t & 1;
            uint32_t* oHi = hstate + (size_t)(2 * ob) * HS;
            uint32_t* oLo = oHi + HS;
#pragma unroll
            for (int rr = 0; rr < 2; rr++) {
                int rb = w * 16 + g + rr * 8;
                size_t trow = (dir == 0) ? ((size_t)t * B_ + rb)
                                         : ((size_t)(15 - t) * B_ + rb);
                const float* xp = XpAll + trow * (8 * D_) + (dir ? 4 * D_ : 0);
                float hvv[2];
#pragma unroll
                for (int cc = 0; cc < 2; cc++) {
                    int d  = d0 + 2 * tq + cc;
                    int vi = rr * 2 + cc;
                    float iv = acc[0][vi] + xp[0 * D_ + d];
                    float fv = acc[1][vi] + xp[1 * D_ + d];
                    float gv = acc[2][vi] + xp[2 * D_ + d];
                    float ov = acc[3][vi] + xp[3 * D_ + d];
                    float co = creg[vi];
                    float si = 1.f / (1.f + expf(-iv));
                    float sf = 1.f / (1.f + expf(-fv));
                    float so = 1.f / (1.f + expf(-ov));
                    float cn = sf * co + si * tanhf(gv);
                    float hv = so * tanhf(cn);
                    creg[vi] = cn;
                    hvv[cc] = hv;
                    if (outF32)
                        outF32[trow * (2 * D_) + D_ * dir + d] = hv;
                }
                uint32_t hw, lw;
                split2(hvv[0], hvv[1], hw, lw);
                int word = (d0 >> 1) + tq;
                oHi[(size_t)(dir * 64 + rb) * 256 + word] = hw;
                oLo[(size_t)(dir * 64 + rb) * 256 + word] = lw;
                uint32_t ohw, olw;
                split2h(hvv[0], hvv[1], ohw, olw);
                size_t ow = trow * 512 + 256 * dir + word;
                outP[ow] = ohw;
                outP[OUT_LO + ow] = olw;
            }
        }
        grid_barrier(t);
    }
}

// ------------------------- attention score + softmax -------------------------
__global__ __launch_bounds__(256) void att_softmax_kernel(
    const float* __restrict__ att1, const float* __restrict__ att2,
    const float* __restrict__ Wfull, float* __restrict__ alpha)
{
    __shared__ float a2s[A_];
    __shared__ float wfl[A_];
    __shared__ float attv[P_];
    __shared__ float red[256];

    int tid = threadIdx.x;
    int t = blockIdx.x >> 6;
    int b = blockIdx.x & 63;

    const float* a2 = att2 + ((size_t)t * B_ + b) * A_;
#pragma unroll
    for (int i = 0; i < 2; i++) {
        int a = tid + i * 256;
        a2s[a] = a2[a];
        wfl[a] = Wfull[a];
    }
    __syncthreads();

    int warp = tid >> 5, lane = tid & 31;
    for (int p = warp; p < P_; p += 8) {
        const float* a1 = att1 + ((size_t)b * P_ + p) * A_;
        float s = 0.f;
        for (int a = lane; a < A_; a += 32) {
            float v = a1[a] + a2s[a];
            s += fmaxf(v, 0.f) * wfl[a];
        }
#pragma unroll
        for (int off = 16; off; off >>= 1) s += __shfl_xor_sync(0xffffffffu, s, off);
        if (lane == 0) attv[p] = s;
    }
    __syncthreads();

    float x = attv[tid];
    red[tid] = x;
    __syncthreads();
    for (int s = 128; s; s >>= 1) {
        if (tid < s) red[tid] = fmaxf(red[tid], red[tid + s]);
        __syncthreads();
    }
    float mx = red[0];
    __syncthreads();
    float e = expf(x - mx);
    red[tid] = e;
    __syncthreads();
    for (int s = 128; s; s >>= 1) {
        if (tid < s) red[tid] += red[tid + s];
        __syncthreads();
    }
    float sum = red[0];
    alpha[((size_t)t * B_ + b) * P_ + tid] = e / sum;
}

// awe + gate fused: aweP fp16 planes + gate scalars (per b block, 512 thr)
__global__ __launch_bounds__(512) void awe_gate_kernel(
    const float* __restrict__ alpha, const float* __restrict__ fh,
    const float* __restrict__ hidden,
    const float* __restrict__ Wg, const float* __restrict__ bg,
    uint32_t* __restrict__ aweP, float* __restrict__ gate)
{
    __shared__ float al[T_][P_];
    __shared__ float gred[16][T_][2];
    const size_t AW_LO = (size_t)1024 * 256;
    const int F = 2 * D_ + E_;
    int b = blockIdx.x;
    int tid = threadIdx.x;
    int wid = tid >> 5, lane = tid & 31;
#pragma unroll
    for (int i = 0; i < 8; i++) {
        int idx = tid + i * 512;
        int t = idx >> 8, p = idx & 255;
        al[t][p] = alpha[((size_t)t * B_ + b) * P_ + p];
    }
    __syncthreads();
    float acc[T_];
#pragma unroll
    for (int t = 0; t < T_; t++) acc[t] = 0.f;
    const float* fhb = fh + (size_t)b * P_ * E_;
    for (int p = 0; p < P_; p++) {
        float v = fhb[(size_t)p * E_ + tid];
#pragma unroll
        for (int t = 0; t < T_; t++) acc[t] += al[t][p] * v;
    }
    // gate weight columns for this thread
    float wa0 = Wg[1024 + tid], wa1 = Wg[F + 1024 + tid];
    float wh00 = Wg[tid], wh01 = Wg[tid + 512];
    float wh10 = Wg[F + tid], wh11 = Wg[F + tid + 512];
#pragma unroll
    for (int t = 0; t < T_; t++) {
        size_t trow = (size_t)t * B_ + b;
        // aweP planes
        float other = __shfl_xor_sync(0xffffffffu, acc[t], 1);
        if ((tid & 1) == 0) {
            uint32_t hw, lw;
            split2h(acc[t], other, hw, lw);
            aweP[trow * 256 + (tid >> 1)] = hw;
            aweP[AW_LO + trow * 256 + (tid >> 1)] = lw;
        }
        // gate partials
        float hv0 = hidden[trow * (2 * D_) + tid];
        float hv1 = hidden[trow * (2 * D_) + tid + 512];
        float p0 = acc[t] * wa0 + hv0 * wh00 + hv1 * wh01;
        float p1 = acc[t] * wa1 + hv0 * wh10 + hv1 * wh11;
#pragma unroll
        for (int off = 16; off; off >>= 1) {
            p0 += __shfl_xor_sync(0xffffffffu, p0, off);
            p1 += __shfl_xor_sync(0xffffffffu, p1, off);
        }
        if (lane == 0) { gred[wid][t][0] = p0; gred[wid][t][1] = p1; }
    }
    __syncthreads();
    if (tid < T_) {
        float z0 = 0.f, z1 = 0.f;
#pragma unroll
        for (int w = 0; w < 16; w++) { z0 += gred[w][tid][0]; z1 += gred[w][tid][1]; }
        z0 += bg[0]; z1 += bg[1];
        float g0 = 1.f / (1.f + expf(z1 - z0));
        size_t row = (size_t)tid * B_ + b;
        gate[row * 2]     = g0;
        gate[row * 2 + 1] = 1.f - g0;
    }
}

// ------------------------------ side-stream infra ----------------------------
namespace {
struct SideInfra {
    cudaStream_t s = nullptr;
    cudaEvent_t fork = nullptr, evPk1 = nullptr, join = nullptr, evL2 = nullptr, evFcH = nullptr;
    bool ok = false;
    SideInfra() {
        if (cudaStreamCreateWithFlags(&s, cudaStreamNonBlocking) != cudaSuccess) return;
        if (cudaEventCreateWithFlags(&fork, cudaEventDisableTiming) != cudaSuccess) return;
        if (cudaEventCreateWithFlags(&evPk1, cudaEventDisableTiming) != cudaSuccess) return;
        if (cudaEventCreateWithFlags(&join, cudaEventDisableTiming) != cudaSuccess) return;
        if (cudaEventCreateWithFlags(&evL2, cudaEventDisableTiming) != cudaSuccess) return;
        if (cudaEventCreateWithFlags(&evFcH, cudaEventDisableTiming) != cudaSuccess) return;
        ok = true;
    }
};
SideInfra g_side;
}

// ------------------------------ launcher ------------------------------------
static inline int packGrid(int N, int K) { return ((N / 8) * (K / 16) * 32 + 255) / 256; }
static inline int packGrid2(int N, int K) { return (2 * (N / 8) * (K / 16) * 32 + 255) / 256; }

extern "C" void kernel_launch(void* const* d_in, const int* in_sizes, int n_in,
                              void* d_out, int out_size)
{
    const float* enc   = (const float*)d_in[0];
    const float* Wih1  = (const float*)d_in[1];
    const float* Whh1  = (const float*)d_in[2];
    const float* bih1  = (const float*)d_in[3];
    const float* bhh1  = (const float*)d_in[4];
    const float* Wih1r = (const float*)d_in[5];
    const float* Whh1r = (const float*)d_in[6];
    const float* bih1r = (const float*)d_in[7];
    const float* bhh1r = (const float*)d_in[8];
    const float* Wih2  = (const float*)d_in[9];
    const float* Whh2  = (const float*)d_in[10];
    const float* bih2  = (const float*)d_in[11];
    const float* bhh2  = (const float*)d_in[12];
    const float* Wih2r = (const float*)d_in[13];
    const float* Whh2r = (const float*)d_in[14];
    const float* bih2r = (const float*)d_in[15];
    const float* bhh2r = (const float*)d_in[16];
    const float* Wenc  = (const float*)d_in[17];
    const float* benc  = (const float*)d_in[18];
    const float* Wdec  = (const float*)d_in[19];
    const float* bdec  = (const float*)d_in[20];
    const float* Wfull = (const float*)d_in[21];
    // d_in[22] = bfull: softmax-shift-invariant, skipped.
    const float* Wg    = (const float*)d_in[23];
    const float* bg    = (const float*)d_in[24];
    const float* Wfc   = (const float*)d_in[25];
    const float* bfc   = (const float*)d_in[26];
    float* out = (float*)d_out;

    float *fh, *XpAll1, *XpAll2, *hidden, *att1, *att2, *alpha;
    float *bAll1, *bAll2, *fcH, *gate;
    uint32_t *featsP, *fhP, *x2P, *hidP, *aweP, *hstate;
    uint4 *Whh1p, *Whh2p;
    uint2 *WihAll1p, *WihAll2p, *Wencp, *Wdecp, *WfcHp, *WfcAp;
    cudaGetSymbolAddress((void**)&fh,      g_fh);
    cudaGetSymbolAddress((void**)&XpAll1,  g_XpAll1);
    cudaGetSymbolAddress((void**)&XpAll2,  g_XpAll2);
    cudaGetSymbolAddress((void**)&hidden,  g_hidden);
    cudaGetSymbolAddress((void**)&att1,    g_att1);
    cudaGetSymbolAddress((void**)&att2,    g_att2);
    cudaGetSymbolAddress((void**)&alpha,   g_alpha);
    cudaGetSymbolAddress((void**)&bAll1,   g_bAll1);
    cudaGetSymbolAddress((void**)&bAll2,   g_bAll2);
    cudaGetSymbolAddress((void**)&fcH,     g_fcH);
    cudaGetSymbolAddress((void**)&gate,    g_gate);
    cudaGetSymbolAddress((void**)&featsP,  g_featsP);
    cudaGetSymbolAddress((void**)&fhP,     g_fhP);
    cudaGetSymbolAddress((void**)&x2P,     g_x2P);
    cudaGetSymbolAddress((void**)&hidP,    g_hidP);
    cudaGetSymbolAddress((void**)&aweP,    g_aweP);
    cudaGetSymbolAddress((void**)&hstate,  g_hstate);
    cudaGetSymbolAddress((void**)&WihAll1p, g_WihAll1p);
    cudaGetSymbolAddress((void**)&WihAll2p, g_WihAll2p);
    cudaGetSymbolAddress((void**)&Whh1p,   g_Whh1p);
    cudaGetSymbolAddress((void**)&Whh2p,   g_Whh2p);
    cudaGetSymbolAddress((void**)&Wencp,   g_Wencp);
    cudaGetSymbolAddress((void**)&Wdecp,   g_Wdecp);
    cudaGetSymbolAddress((void**)&WfcHp,   g_WfcHp);
    cudaGetSymbolAddress((void**)&WfcAp,   g_WfcAp);

    const int off1h = (2048 / 8) * (512 / 16) * 32;    // fwd half, layer 1 (uint2)
    const int off2h = (2048 / 8) * (1024 / 16) * 32;   // fwd half, layer 2 (uint2)
    const int offWh = (2048 / 8) * (512 / 16) * 32;    // Whh fwd half (uint4)

    bool useSide = g_side.ok;
    cudaStream_t sd = useSide ? g_side.s : (cudaStream_t)0;

    if (useSide) {
        cudaEventRecord(g_side.fork, 0);
        cudaStreamWaitEvent(sd, g_side.fork, 0);
    }

    // ---- side stream part 1: layer-1 packs ----
    pack_wh2<<<packGrid2(2048, 512), 256, 0, sd>>>(Wih1, Wih1r, WihAll1p, 2048, 512, off1h);
    pack_w2<<<packGrid2(2048, 512), 256, 0, sd>>>(Whh1, Whh1r, Whh1p, 2048, 512, offWh);
    bias_all<<<32, 256, 0, sd>>>(bih1, bhh1, bih1r, bhh1r, bih2, bhh2, bih2r, bhh2r,
                                 bAll1, bAll2);
    if (useSide) cudaEventRecord(g_side.evPk1, sd);

    // ---- main stream: layer-1 path ----
    feats_kernel<<<(T_ * B_ * 256 + 255) / 256, 256>>>(enc, featsP);
    if (useSide) cudaStreamWaitEvent(0, g_side.evPk1, 0);
    gemm_f16x2<<<dim3(64, 8), 256>>>(featsP, WihAll1p, bAll1,
                                     XpAll1, T_ * B_, 8 * D_, E_);
    lstm_persist<<<128, 256>>>(XpAll1, Whh1p, hstate, x2P, nullptr, offWh);

    // ---- side stream part 2: att1 path + layer-2/fc packs ----
    transpose_fh_kernel<<<dim3(16, 8, 64), dim3(32, 8), 0, sd>>>(enc, fh, fhP);
    pack_wh<<<packGrid(512, 512), 256, 0, sd>>>(Wenc, Wencp, 512, 512, 512, 0);
    gemm_f16x2<<<dim3(8, 128), 256, 0, sd>>>(fhP, Wencp, benc, att1, B_ * P_, A_, E_);
    pack_wh<<<packGrid(512, 1024), 256, 0, sd>>>(Wdec, Wdecp, 512, 1024, 1024, 0);
    pack_wh2<<<packGrid2(2048, 1024), 256, 0, sd>>>(Wih2, Wih2r, WihAll2p, 2048, 1024, off2h);
    pack_w2<<<packGrid2(2048, 512), 256, 0, sd>>>(Whh2, Whh2r, Whh2p, 2048, 512, offWh);
    pack_wh<<<packGrid(5000, 1024), 256, 0, sd>>>(Wfc, WfcHp, 5000, 1024, 1536, 0);
    pack_wh<<<packGrid(5000, 512),  256, 0, sd>>>(Wfc, WfcAp, 5000, 512, 1536, 1024);
    if (useSide) cudaEventRecord(g_side.join, sd);

    if (useSide) cudaStreamWaitEvent(0, g_side.join, 0);

    // ---- layer-2 ----
    gemm_f16x2<<<dim3(64, 8), 256>>>(x2P, WihAll2p, bAll2,
                                     XpAll2, T_ * B_, 8 * D_, 2 * D_);
    lstm_persist<<<128, 256>>>(XpAll2, Whh2p, hstate, hidP, hidden, offWh);
    if (useSide) {
        cudaEventRecord(g_side.evL2, 0);
        cudaStreamWaitEvent(sd, g_side.evL2, 0);
    }

    // fcH = hidden @ WfcH.T (side stream, overlaps attention tail)
    gemm_f16x2<<<dim3((V_ + 63) / 64, 8), 256, 0, sd>>>(hidP, WfcHp, nullptr,
                                                        fcH, T_ * B_, V_, 2 * D_);
    if (useSide) cudaEventRecord(g_side.evFcH, sd);

    // ---- attention tail (main) ----
    gemm_f16x2<<<dim3(8, 8), 256>>>(hidP, Wdecp, bdec, att2, T_ * B_, A_, 2 * D_);
    att_softmax_kernel<<<T_ * B_, 256>>>(att1, att2, Wfull, alpha);
    awe_gate_kernel<<<B_, 512>>>(alpha, fh, hidden, Wg, bg, aweP, gate);
    if (useSide) cudaStreamWaitEvent(0, g_side.evFcH, 0);
    gemm_f16x2_fc<<<dim3((V_ + 63) / 64, 8), 256>>>(aweP, WfcAp, fcH, gate, bfc,
                                                    out, T_ * B_, V_, E_);
}

// round 16
// speedup vs baseline: 1.0206x; 1.0206x over previous
#include <cuda_runtime.h>
#include <cuda_bf16.h>
#include <cuda_fp16.h>
#include <math.h>
#include <stdint.h>

// ---------------------------------------------------------------------------
// DecoderWithAttention: B=64, E=512, H=W=16, T=16, D=512, A=512, V=5000
// Mixed-precision mma.sync pipeline (R14 structure + fused awe/gate):
//  - LSTM recurrence (Whh, h-state): bf16 hi/lo 3-pass (proven)
//  - Xp projections + attention + fc: fp16 hi/lo 2-pass (B hi-only), BK=16
//  - fc distributed: out = g0*(hidden@WfcH.T) + g1*(awe@WfcA.T) + bfc,
//    combine fused into fcA GEMM; gate fused into awe kernel.
// ---------------------------------------------------------------------------

#define B_ 64
#define E_ 512
#define T_ 16
#define D_ 512
#define P_ 256
#define A_ 512
#define V_ 5000

// ------------------------------ scratch ------------------------------------
__device__ float g_fh    [B_ * P_ * E_];
__device__ float g_XpAll1[T_ * B_ * 8 * D_];
__device__ float g_XpAll2[T_ * B_ * 8 * D_];
__device__ float g_hidden[T_ * B_ * 2 * D_];
__device__ float g_att1  [B_ * P_ * A_];
__device__ float g_att2  [T_ * B_ * A_];
__device__ float g_alpha [T_ * B_ * P_];
__device__ float g_bAll1 [8 * D_];
__device__ float g_bAll2 [8 * D_];
__device__ float g_fcH   [T_ * B_ * V_];
__device__ float g_gate  [T_ * B_ * 2];

// A-operand hi/lo planes (uint32 = 2 packed halves; lo plane at +M*K/2)
__device__ uint32_t g_featsP[2 * 1024 * 256];   // fp16 (Xp1)
__device__ uint32_t g_fhP  [2 * 16384 * 256];   // fp16 (att1)
__device__ uint32_t g_x2P  [2 * 1024 * 512];    // fp16 (Xp2)
__device__ uint32_t g_hidP [2 * 1024 * 512];    // fp16 (att2 + fcH)
__device__ uint32_t g_aweP [2 * 1024 * 256];    // fp16 (fcA)
__device__ uint32_t g_hstate[4 * 128 * 256];    // bf16 recurrence state

// bf16 fragment-packed weights (recurrence): [n8][k16][lane] uint4
__device__ uint4 g_Whh1p [(2048/8) * (512/16) * 32];
__device__ uint4 g_Whh1rp[(2048/8) * (512/16) * 32];
__device__ uint4 g_Whh2p [(2048/8) * (512/16) * 32];
__device__ uint4 g_Whh2rp[(2048/8) * (512/16) * 32];
// fp16 hi-only packed weights: [n8][k16][lane] uint2 {h0,h1}
__device__ uint2 g_WihAll1p[(4096/8) * (512/16)  * 32];
__device__ uint2 g_WihAll2p[(4096/8) * (1024/16) * 32];
__device__ uint2 g_Wencp [(512/8)  * (512/16) * 32];
__device__ uint2 g_Wdecp [(512/8)  * (1024/16)* 32];
__device__ uint2 g_WfcHp [(5000/8) * (1024/16)* 32];
__device__ uint2 g_WfcAp [(5000/8) * (512/16) * 32];

__device__ int g_bar_cnt = 0;
__device__ volatile int g_bar_sense = 0;

// ------------------------------ helpers ------------------------------------
__device__ __forceinline__ void mma_bf16(float* d, const uint32_t* a, const uint32_t* b) {
    asm volatile(
        "mma.sync.aligned.m16n8k16.row.col.f32.bf16.bf16.f32 "
        "{%0,%1,%2,%3}, {%4,%5,%6,%7}, {%8,%9}, {%0,%1,%2,%3};\n"
        : "+f"(d[0]), "+f"(d[1]), "+f"(d[2]), "+f"(d[3])
        : "r"(a[0]), "r"(a[1]), "r"(a[2]), "r"(a[3]), "r"(b[0]), "r"(b[1]));
}
__device__ __forceinline__ void mma_f16(float* d, const uint32_t* a, const uint32_t* b) {
    asm volatile(
        "mma.sync.aligned.m16n8k16.row.col.f32.f16.f16.f32 "
        "{%0,%1,%2,%3}, {%4,%5,%6,%7}, {%8,%9}, {%0,%1,%2,%3};\n"
        : "+f"(d[0]), "+f"(d[1]), "+f"(d[2]), "+f"(d[3])
        : "r"(a[0]), "r"(a[1]), "r"(a[2]), "r"(a[3]), "r"(b[0]), "r"(b[1]));
}

__device__ __forceinline__ void split2(float x0, float x1, uint32_t& hi, uint32_t& lo) {
    __nv_bfloat16 h0 = __float2bfloat16_rn(x0);
    __nv_bfloat16 h1 = __float2bfloat16_rn(x1);
    __nv_bfloat162 hp = __halves2bfloat162(h0, h1);
    hi = *(uint32_t*)&hp;
    __nv_bfloat162 lp = __floats2bfloat162_rn(x0 - __bfloat162float(h0),
                                              x1 - __bfloat162float(h1));
    lo = *(uint32_t*)&lp;
}
__device__ __forceinline__ void split2h(float x0, float x1, uint32_t& hi, uint32_t& lo) {
    __half h0 = __float2half_rn(x0);
    __half h1 = __float2half_rn(x1);
    __half2 hp = __halves2half2(h0, h1);
    hi = *(uint32_t*)&hp;
    __half2 lp = __floats2half2_rn(x0 - __half2float(h0), x1 - __half2float(h1));
    lo = *(uint32_t*)&lp;
}

// bf16 hi/lo fragment pack (recurrence weights)
__global__ void pack_w(const float* __restrict__ W, uint4* __restrict__ Wp,
                       int N, int K) {
    int idx = blockIdx.x * 256 + threadIdx.x;
    int K16 = K >> 4;
    int total = (N >> 3) * K16 * 32;
    if (idx >= total) return;
    int lane = idx & 31;
    int k16 = (idx >> 5) % K16;
    int n8 = idx / (32 * K16);
    int g = lane >> 2, tq = lane & 3;
    const float* src = W + (size_t)(n8 * 8 + g) * K + k16 * 16;
    uint4 o;
    split2(src[2 * tq],     src[2 * tq + 1], o.x, o.z);
    split2(src[2 * tq + 8], src[2 * tq + 9], o.y, o.w);
    Wp[idx] = o;
}

// fp16 hi-only fragment pack with source row-stride/column-offset
__global__ void pack_wh(const float* __restrict__ W, uint2* __restrict__ Wp,
                        int N, int K, int srcStride, int colOff) {
    int idx = blockIdx.x * 256 + threadIdx.x;
    int K16 = K >> 4;
    int total = (N >> 3) * K16 * 32;
    if (idx >= total) return;
    int lane = idx & 31;
    int k16 = (idx >> 5) % K16;
    int n8 = idx / (32 * K16);
    int g = lane >> 2, tq = lane & 3;
    const float* src = W + (size_t)(n8 * 8 + g) * srcStride + colOff + k16 * 16;
    __half2 a = __floats2half2_rn(src[2 * tq],     src[2 * tq + 1]);
    __half2 b = __floats2half2_rn(src[2 * tq + 8], src[2 * tq + 9]);
    Wp[idx] = make_uint2(*(uint32_t*)&a, *(uint32_t*)&b);
}

__global__ void bias_combine(const float* __restrict__ b1f, const float* __restrict__ b2f,
                             const float* __restrict__ b1r, const float* __restrict__ b2r,
                             float* __restrict__ out) {
    int i = blockIdx.x * 256 + threadIdx.x;
    if (i >= 8 * D_) return;
    out[i] = (i < 4 * D_) ? (b1f[i] + b2f[i]) : (b1r[i - 4 * D_] + b2r[i - 4 * D_]);
}

// fh[b][p][e] = enc[b][e][p]; emits fp32 fh + fp16 hi/lo planes
__global__ void transpose_fh_kernel(const float* __restrict__ enc, float* __restrict__ fh,
                                    uint32_t* __restrict__ fhP) {
    __shared__ float tile[32][33];
    const size_t FH_LO = (size_t)16384 * 256;
    int b  = blockIdx.z;
    int e0 = blockIdx.x * 32;
    int p0 = blockIdx.y * 32;
    int x = threadIdx.x;
#pragma unroll
    for (int i = 0; i < 4; i++) {
        int y = threadIdx.y + i * 8;
        tile[y][x] = enc[((size_t)b * E_ + e0 + y) * P_ + p0 + x];
    }
    __syncthreads();
    int it = threadIdx.y * 32 + threadIdx.x;
#pragma unroll
    for (int i = 0; i < 2; i++) {
        int item = it + i * 256;
        int yy = item >> 4;
        int xx = item & 15;
        float v0 = tile[2 * xx][yy];
        float v1 = tile[2 * xx + 1][yy];
        size_t row = (size_t)b * P_ + p0 + yy;
        fh[row * E_ + e0 + 2 * xx]     = v0;
        fh[row * E_ + e0 + 2 * xx + 1] = v1;
        uint32_t hw, lw;
        split2h(v0, v1, hw, lw);
        size_t w = row * 256 + (e0 >> 1) + xx;
        fhP[w] = hw;
        fhP[FH_LO + w] = lw;
    }
}

// feats fp16 planes
__global__ void feats_kernel(const float* __restrict__ enc, uint32_t* __restrict__ featsP) {
    const size_t F_LO = (size_t)1024 * 256;
    int gi = blockIdx.x * blockDim.x + threadIdx.x;
    if (gi >= T_ * B_ * 256) return;
    int t = gi & 15;
    int e2 = (gi >> 4) & 255;
    int b = gi >> 12;
    const float* s0 = enc + ((size_t)b * E_ + 2 * e2) * P_ + t;
    const float* s1 = s0 + P_;
    float a0 = 0.f, a1 = 0.f;
#pragma unroll
    for (int h = 0; h < 16; h++) { a0 += s0[h * 16]; a1 += s1[h * 16]; }
    uint32_t hw, lw;
    split2h(a0 * (1.f / 16.f), a1 * (1.f / 16.f), hw, lw);
    size_t w = ((size_t)t * B_ + b) * 256 + e2;
    featsP[w] = hw;
    featsP[F_LO + w] = lw;
}

#define ASW 12

// ---------------------- fp16x2 GEMM (2-pass, B hi-only) ----------------------
__global__ __launch_bounds__(256, 2) void gemm_f16x2(
    const uint32_t* __restrict__ Ap, const uint2* __restrict__ Wp,
    const float* __restrict__ b1,
    float* __restrict__ C, int M, int N, int K)
{
    __shared__ __align__(16) uint32_t Ah[2][128][ASW];
    __shared__ __align__(16) uint32_t Al[2][128][ASW];

    int tid  = threadIdx.x;
    int wid  = tid >> 5, lane = tid & 31;
    int g = lane >> 2, tq = lane & 3;
    int m0 = blockIdx.y * 128, n0 = blockIdx.x * 64;
    int wm = wid * 16;
    int K2 = K >> 1, K16 = K >> 4;
    int nTiles = N >> 3;
    size_t loOff = (size_t)M * K2;

    const uint2* bp[8];
    bool bok[8];
#pragma unroll
    for (int j = 0; j < 8; j++) {
        int n8 = (n0 >> 3) + j;
        bok[j] = (n8 < nTiles);
        bp[j] = Wp + ((size_t)(bok[j] ? n8 : 0) * K16) * 32 + lane;
    }

    float acc[8][4];
#pragma unroll
    for (int j = 0; j < 8; j++)
#pragma unroll
        for (int v = 0; v < 4; v++) acc[j][v] = 0.f;

    int r = tid >> 1, half = tid & 1;
    const uint4* aH = (const uint4*)(Ap + (size_t)(m0 + r) * K2) + half;
    const uint4* aL = (const uint4*)(Ap + loOff + (size_t)(m0 + r) * K2) + half;

    {
        uint4 h = aH[0], l = aL[0];
        *(uint4*)&Ah[0][r][half * 4] = h;
        *(uint4*)&Al[0][r][half * 4] = l;
    }
    __syncthreads();

    int buf = 0;
    for (int kt = 0; kt < K16; kt++) {
        bool more = (kt + 1) < K16;
        uint4 nh, nl;
        if (more) {
            nh = aH[(kt + 1) * 2];
            nl = aL[(kt + 1) * 2];
        }
        uint32_t ah[4], al[4];
        {
            int rA = wm + g, rB = rA + 8;
            ah[0] = Ah[buf][rA][tq];     ah[1] = Ah[buf][rB][tq];
            ah[2] = Ah[buf][rA][tq + 4]; ah[3] = Ah[buf][rB][tq + 4];
            al[0] = Al[buf][rA][tq];     al[1] = Al[buf][rB][tq];
            al[2] = Al[buf][rA][tq + 4]; al[3] = Al[buf][rB][tq + 4];
        }
#pragma unroll
        for (int j = 0; j < 8; j++) {
            uint2 bv = bok[j] ? bp[j][kt * 32] : make_uint2(0u, 0u);
            uint32_t bh[2] = {bv.x, bv.y};
            mma_f16(acc[j], ah, bh);
            mma_f16(acc[j], al, bh);
        }
        if (more) {
            *(uint4*)&Ah[buf ^ 1][r][half * 4] = nh;
            *(uint4*)&Al[buf ^ 1][r][half * 4] = nl;
            __syncthreads();
            buf ^= 1;
        }
    }

#pragma unroll
    for (int j = 0; j < 8; j++) {
        int rr = m0 + wm + g;
        int c0 = n0 + j * 8 + 2 * tq;
#pragma unroll
        for (int cc = 0; cc < 2; cc++) {
            int c = c0 + cc;
            if (c < N) {
                float bias = b1 ? b1[c] : 0.f;
                C[(size_t)rr * N + c]       = acc[j][cc]     + bias;
                C[(size_t)(rr + 8) * N + c] = acc[j][2 + cc] + bias;
            }
        }
    }
}

// ------------- fp16x2 GEMM with fused gate-combine epilogue ------------------
// out[r][c] = g0[r]*fcH[r][c] + g1[r]*acc[r][c] + bfc[c]
__global__ __launch_bounds__(256, 2) void gemm_f16x2_fc(
    const uint32_t* __restrict__ Ap, const uint2* __restrict__ Wp,
    const float* __restrict__ fcH, const float* __restrict__ gate,
    const float* __restrict__ bfc,
    float* __restrict__ C, int M, int N, int K)
{
    __shared__ __align__(16) uint32_t Ah[2][128][ASW];
    __shared__ __align__(16) uint32_t Al[2][128][ASW];

    int tid  = threadIdx.x;
    int wid  = tid >> 5, lane = tid & 31;
    int g = lane >> 2, tq = lane & 3;
    int m0 = blockIdx.y * 128, n0 = blockIdx.x * 64;
    int wm = wid * 16;
    int K2 = K >> 1, K16 = K >> 4;
    int nTiles = N >> 3;
    size_t loOff = (size_t)M * K2;

    const uint2* bp[8];
    bool bok[8];
#pragma unroll
    for (int j = 0; j < 8; j++) {
        int n8 = (n0 >> 3) + j;
        bok[j] = (n8 < nTiles);
        bp[j] = Wp + ((size_t)(bok[j] ? n8 : 0) * K16) * 32 + lane;
    }

    float acc[8][4];
#pragma unroll
    for (int j = 0; j < 8; j++)
#pragma unroll
        for (int v = 0; v < 4; v++) acc[j][v] = 0.f;

    int r = tid >> 1, half = tid & 1;
    const uint4* aH = (const uint4*)(Ap + (size_t)(m0 + r) * K2) + half;
    const uint4* aL = (const uint4*)(Ap + loOff + (size_t)(m0 + r) * K2) + half;

    {
        uint4 h = aH[0], l = aL[0];
        *(uint4*)&Ah[0][r][half * 4] = h;
        *(uint4*)&Al[0][r][half * 4] = l;
    }
    __syncthreads();

    int buf = 0;
    for (int kt = 0; kt < K16; kt++) {
        bool more = (kt + 1) < K16;
        uint4 nh, nl;
        if (more) {
            nh = aH[(kt + 1) * 2];
            nl = aL[(kt + 1) * 2];
        }
        uint32_t ah[4], al[4];
        {
            int rA = wm + g, rB = rA + 8;
            ah[0] = Ah[buf][rA][tq];     ah[1] = Ah[buf][rB][tq];
            ah[2] = Ah[buf][rA][tq + 4]; ah[3] = Ah[buf][rB][tq + 4];
            al[0] = Al[buf][rA][tq];     al[1] = Al[buf][rB][tq];
            al[2] = Al[buf][rA][tq + 4]; al[3] = Al[buf][rB][tq + 4];
        }
#pragma unroll
        for (int j = 0; j < 8; j++) {
            uint2 bv = bok[j] ? bp[j][kt * 32] : make_uint2(0u, 0u);
            uint32_t bh[2] = {bv.x, bv.y};
            mma_f16(acc[j], ah, bh);
            mma_f16(acc[j], al, bh);
        }
        if (more) {
            *(uint4*)&Ah[buf ^ 1][r][half * 4] = nh;
            *(uint4*)&Al[buf ^ 1][r][half * 4] = nl;
            __syncthreads();
            buf ^= 1;
        }
    }

    int rr0 = m0 + wm + g;
    float g0a = gate[(size_t)rr0 * 2],       g1a = gate[(size_t)rr0 * 2 + 1];
    float g0b = gate[(size_t)(rr0 + 8) * 2], g1b = gate[(size_t)(rr0 + 8) * 2 + 1];
#pragma unroll
    for (int j = 0; j < 8; j++) {
        int c0 = n0 + j * 8 + 2 * tq;
#pragma unroll
        for (int cc = 0; cc < 2; cc++) {
            int c = c0 + cc;
            if (c < N) {
                float bias = bfc[c];
                size_t ia = (size_t)rr0 * N + c;
                size_t ib = (size_t)(rr0 + 8) * N + c;
                C[ia] = g0a * fcH[ia] + g1a * acc[j][cc]     + bias;
                C[ib] = g0b * fcH[ib] + g1b * acc[j][2 + cc] + bias;
            }
        }
    }
}

// ---------------------- persistent LSTM (split-K, bf16 3-pass) ---------------
__device__ __forceinline__ void grid_barrier(int step) {
    __threadfence();
    __syncthreads();
    if (threadIdx.x == 0) {
        int target = (step + 1) & 1;
        if (atomicAdd(&g_bar_cnt, 1) == (int)gridDim.x - 1) {
            atomicExch(&g_bar_cnt, 0);
            __threadfence();
            g_bar_sense = target;
        } else {
            while (g_bar_sense != target) __nanosleep(32);
        }
        __threadfence();
    }
    __syncthreads();
}

// 128 blocks x 256 threads. dir = bid>>6, d-slice = bid&63 (8 d each).
__global__ __launch_bounds__(256) void lstm_persist(
    const float* __restrict__ XpAll,
    const uint4* __restrict__ Whfp, const uint4* __restrict__ Whrp,
    uint32_t* __restrict__ hstate,
    uint32_t* __restrict__ outP, float* __restrict__ outF32)
{
    __shared__ __align__(16) uint32_t Hh[2][128][ASW];
    __shared__ __align__(16) uint32_t Hl[2][128][ASW];
    __shared__ float red[4][32][16];

    const int HS = 128 * 256;
    const size_t OUT_LO = (size_t)1024 * 512;

    int tid = threadIdx.x;
    int w = tid >> 5, lane = tid & 31;
    int g = lane >> 2, tq = lane & 3;
    int dir = blockIdx.x >> 6;
    int idx = blockIdx.x & 63;
    int d0 = idx * 8;
    const uint4* Whp = dir ? Whrp : Whfp;
    const int K16tot = D_ >> 4;
    int kg = w >> 2;
    int wl = w & 3;

    const uint4* bp[4];
#pragma unroll
    for (int j = 0; j < 4; j++)
        bp[j] = Whp + ((size_t)(j * 64 + idx) * K16tot) * 32 + lane;

    int sKg = tid >> 7;
    int sR  = (tid >> 1) & 63;
    int sKh = tid & 1;

    float creg[4] = {0.f, 0.f, 0.f, 0.f};

    for (int t = 0; t < T_; t++) {
        float acc[4][4];
#pragma unroll
        for (int j = 0; j < 4; j++)
#pragma unroll
            for (int v = 0; v < 4; v++) acc[j][v] = 0.f;

        if (t > 0) {
            int ib = (t - 1) & 1;
            const uint32_t* hHi = hstate + (size_t)(2 * ib) * HS;
            const uint32_t* hLo = hHi + HS;
            const uint4* sH = (const uint4*)(hHi + (size_t)(dir * 64 + sR) * 256) + sKg * 32 + sKh;
            const uint4* sL = (const uint4*)(hLo + (size_t)(dir * 64 + sR) * 256) + sKg * 32 + sKh;

            {
                uint4 h = sH[0], l = sL[0];
                *(uint4*)&Hh[0][sKg * 64 + sR][sKh * 4] = h;
                *(uint4*)&Hl[0][sKg * 64 + sR][sKh * 4] = l;
            }
            uint4 breg[4];
#pragma unroll
            for (int j = 0; j < 4; j++) breg[j] = bp[j][(kg * 16) * 32];
            __syncthreads();

            int buf = 0;
            for (int kt = 0; kt < 16; kt++) {
                bool more = (kt + 1) < 16;
                uint4 nh, nl, bnext[4];
                if (more) {
                    nh = sH[(kt + 1) * 2];
                    nl = sL[(kt + 1) * 2];
#pragma unroll
                    for (int j = 0; j < 4; j++) bnext[j] = bp[j][(kg * 16 + kt + 1) * 32];
                }
                int rA = kg * 64 + wl * 16 + g, rB = rA + 8;
                uint32_t ah[4], al[4];
                ah[0] = Hh[buf][rA][tq];     ah[1] = Hh[buf][rB][tq];
                ah[2] = Hh[buf][rA][tq + 4]; ah[3] = Hh[buf][rB][tq + 4];
                al[0] = Hl[buf][rA][tq];     al[1] = Hl[buf][rB][tq];
                al[2] = Hl[buf][rA][tq + 4]; al[3] = Hl[buf][rB][tq + 4];
#pragma unroll
                for (int j = 0; j < 4; j++) {
                    uint32_t bh[2] = {breg[j].x, breg[j].y};
                    uint32_t bl[2] = {breg[j].z, breg[j].w};
                    mma_bf16(acc[j], ah, bh);
                    mma_bf16(acc[j], al, bh);
                    mma_bf16(acc[j], ah, bl);
                }
                if (more) {
                    *(uint4*)&Hh[buf ^ 1][sKg * 64 + sR][sKh * 4] = nh;
                    *(uint4*)&Hl[buf ^ 1][sKg * 64 + sR][sKh * 4] = nl;
                    __syncthreads();
                    buf ^= 1;
#pragma unroll
                    for (int j = 0; j < 4; j++) breg[j] = bnext[j];
                }
            }
            if (w >= 4) {
#pragma unroll
                for (int j = 0; j < 4; j++)
#pragma unroll
                    for (int v = 0; v < 4; v++) red[wl][lane][j * 4 + v] = acc[j][v];
            }
            __syncthreads();
            if (w < 4) {
#pragma unroll
                for (int j = 0; j < 4; j++)
#pragma unroll
                    for (int v = 0; v < 4; v++) acc[j][v] += red[w][lane][j * 4 + v];
            }
        }

        if (w < 4) {
            int ob = t & 1;
            uint32_t* oHi = hstate + (size_t)(2 * ob) * HS;
            uint32_t* oLo = oHi + HS;
#pragma unroll
            for (int rr = 0; rr < 2; rr++) {
                int rb = w * 16 + g + rr * 8;
                size_t trow = (dir == 0) ? ((size_t)t * B_ + rb)
                                         : ((size_t)(15 - t) * B_ + rb);
                const float* xp = XpAll + trow * (8 * D_) + (dir ? 4 * D_ : 0);
                float hvv[2];
#pragma unroll
                for (int cc = 0; cc < 2; cc++) {
                    int d  = d0 + 2 * tq + cc;
                    int vi = rr * 2 + cc;
                    float iv = acc[0][vi] + xp[0 * D_ + d];
                    float fv = acc[1][vi] + xp[1 * D_ + d];
                    float gv = acc[2][vi] + xp[2 * D_ + d];
                    float ov = acc[3][vi] + xp[3 * D_ + d];
                    float co = creg[vi];
                    float si = 1.f / (1.f + expf(-iv));
                    float sf = 1.f / (1.f + expf(-fv));
                    float so = 1.f / (1.f + expf(-ov));
                    float cn = sf * co + si * tanhf(gv);
                    float hv = so * tanhf(cn);
                    creg[vi] = cn;
                    hvv[cc] = hv;
                    if (outF32)
                        outF32[trow * (2 * D_) + D_ * dir + d] = hv;
                }
                uint32_t hw, lw;
                split2(hvv[0], hvv[1], hw, lw);
                int word = (d0 >> 1) + tq;
                oHi[(size_t)(dir * 64 + rb) * 256 + word] = hw;
                oLo[(size_t)(dir * 64 + rb) * 256 + word] = lw;
                uint32_t ohw, olw;
                split2h(hvv[0], hvv[1], ohw, olw);
                size_t ow = trow * 512 + 256 * dir + word;
                outP[ow] = ohw;
                outP[OUT_LO + ow] = olw;
            }
        }
        grid_barrier(t);
    }
}

// ------------------------- attention score + softmax -------------------------
__global__ __launch_bounds__(256) void att_softmax_kernel(
    const float* __restrict__ att1, const float* __restrict__ att2,
    const float* __restrict__ Wfull, float* __restrict__ alpha)
{
    __shared__ float a2s[A_];
    __shared__ float wfl[A_];
    __shared__ float attv[P_];
    __shared__ float red[256];

    int tid = threadIdx.x;
    int t = blockIdx.x >> 6;
    int b = blockIdx.x & 63;

    const float* a2 = att2 + ((size_t)t * B_ + b) * A_;
#pragma unroll
    for (int i = 0; i < 2; i++) {
        int a = tid + i * 256;
        a2s[a] = a2[a];
        wfl[a] = Wfull[a];
    }
    __syncthreads();

    int warp = tid >> 5, lane = tid & 31;
    for (int p = warp; p < P_; p += 8) {
        const float* a1 = att1 + ((size_t)b * P_ + p) * A_;
        float s = 0.f;
        for (int a = lane; a < A_; a += 32) {
            float v = a1[a] + a2s[a];
            s += fmaxf(v, 0.f) * wfl[a];
        }
#pragma unroll
        for (int off = 16; off; off >>= 1) s += __shfl_xor_sync(0xffffffffu, s, off);
        if (lane == 0) attv[p] = s;
    }
    __syncthreads();

    float x = attv[tid];
    red[tid] = x;
    __syncthreads();
    for (int s = 128; s; s >>= 1) {
        if (tid < s) red[tid] = fmaxf(red[tid], red[tid + s]);
        __syncthreads();
    }
    float mx = red[0];
    __syncthreads();
    float e = expf(x - mx);
    red[tid] = e;
    __syncthreads();
    for (int s = 128; s; s >>= 1) {
        if (tid < s) red[tid] += red[tid + s];
        __syncthreads();
    }
    float sum = red[0];
    alpha[((size_t)t * B_ + b) * P_ + tid] = e / sum;
}

// awe + gate fused: aweP fp16 planes + gate scalars (per b block, 512 thr)
__global__ __launch_bounds__(512) void awe_gate_kernel(
    const float* __restrict__ alpha, const float* __restrict__ fh,
    const float* __restrict__ hidden,
    const float* __restrict__ Wg, const float* __restrict__ bg,
    uint32_t* __restrict__ aweP, float* __restrict__ gate)
{
    __shared__ float al[T_][P_];
    __shared__ float gred[16][T_][2];
    const size_t AW_LO = (size_t)1024 * 256;
    const int F = 2 * D_ + E_;
    int b = blockIdx.x;
    int tid = threadIdx.x;
    int wid = tid >> 5, lane = tid & 31;
#pragma unroll
    for (int i = 0; i < 8; i++) {
        int idx = tid + i * 512;
        int t = idx >> 8, p = idx & 255;
        al[t][p] = alpha[((size_t)t * B_ + b) * P_ + p];
    }
    __syncthreads();
    float acc[T_];
#pragma unroll
    for (int t = 0; t < T_; t++) acc[t] = 0.f;
    const float* fhb = fh + (size_t)b * P_ * E_;
    for (int p = 0; p < P_; p++) {
        float v = fhb[(size_t)p * E_ + tid];
#pragma unroll
        for (int t = 0; t < T_; t++) acc[t] += al[t][p] * v;
    }
    float wa0 = Wg[1024 + tid], wa1 = Wg[F + 1024 + tid];
    float wh00 = Wg[tid], wh01 = Wg[tid + 512];
    float wh10 = Wg[F + tid], wh11 = Wg[F + tid + 512];
#pragma unroll
    for (int t = 0; t < T_; t++) {
        size_t trow = (size_t)t * B_ + b;
        float other = __shfl_xor_sync(0xffffffffu, acc[t], 1);
        if ((tid & 1) == 0) {
            uint32_t hw, lw;
            split2h(acc[t], other, hw, lw);
            aweP[trow * 256 + (tid >> 1)] = hw;
            aweP[AW_LO + trow * 256 + (tid >> 1)] = lw;
        }
        float hv0 = hidden[trow * (2 * D_) + tid];
        float hv1 = hidden[trow * (2 * D_) + tid + 512];
        float p0 = acc[t] * wa0 + hv0 * wh00 + hv1 * wh01;
        float p1 = acc[t] * wa1 + hv0 * wh10 + hv1 * wh11;
#pragma unroll
        for (int off = 16; off; off >>= 1) {
            p0 += __shfl_xor_sync(0xffffffffu, p0, off);
            p1 += __shfl_xor_sync(0xffffffffu, p1, off);
        }
        if (lane == 0) { gred[wid][t][0] = p0; gred[wid][t][1] = p1; }
    }
    __syncthreads();
    if (tid < T_) {
        float z0 = 0.f, z1 = 0.f;
#pragma unroll
        for (int w = 0; w < 16; w++) { z0 += gred[w][tid][0]; z1 += gred[w][tid][1]; }
        z0 += bg[0]; z1 += bg[1];
        float g0 = 1.f / (1.f + expf(z1 - z0));
        size_t row = (size_t)tid * B_ + b;
        gate[row * 2]     = g0;
        gate[row * 2 + 1] = 1.f - g0;
    }
}

// ------------------------------ side-stream infra ----------------------------
namespace {
struct SideInfra {
    cudaStream_t s = nullptr;
    cudaEvent_t fork = nullptr, join = nullptr, evL2 = nullptr, evFcH = nullptr;
    bool ok = false;
    SideInfra() {
        if (cudaStreamCreateWithFlags(&s, cudaStreamNonBlocking) != cudaSuccess) return;
        if (cudaEventCreateWithFlags(&fork, cudaEventDisableTiming) != cudaSuccess) return;
        if (cudaEventCreateWithFlags(&join, cudaEventDisableTiming) != cudaSuccess) return;
        if (cudaEventCreateWithFlags(&evL2, cudaEventDisableTiming) != cudaSuccess) return;
        if (cudaEventCreateWithFlags(&evFcH, cudaEventDisableTiming) != cudaSuccess) return;
        ok = true;
    }
};
SideInfra g_side;
}

// ------------------------------ launcher ------------------------------------
static inline int packGrid(int N, int K) { return ((N / 8) * (K / 16) * 32 + 255) / 256; }

extern "C" void kernel_launch(void* const* d_in, const int* in_sizes, int n_in,
                              void* d_out, int out_size)
{
    const float* enc   = (const float*)d_in[0];
    const float* Wih1  = (const float*)d_in[1];
    const float* Whh1  = (const float*)d_in[2];
    const float* bih1  = (const float*)d_in[3];
    const float* bhh1  = (const float*)d_in[4];
    const float* Wih1r = (const float*)d_in[5];
    const float* Whh1r = (const float*)d_in[6];
    const float* bih1r = (const float*)d_in[7];
    const float* bhh1r = (const float*)d_in[8];
    const float* Wih2  = (const float*)d_in[9];
    const float* Whh2  = (const float*)d_in[10];
    const float* bih2  = (const float*)d_in[11];
    const float* bhh2  = (const float*)d_in[12];
    const float* Wih2r = (const float*)d_in[13];
    const float* Whh2r = (const float*)d_in[14];
    const float* bih2r = (const float*)d_in[15];
    const float* bhh2r = (const float*)d_in[16];
    const float* Wenc  = (const float*)d_in[17];
    const float* benc  = (const float*)d_in[18];
    const float* Wdec  = (const float*)d_in[19];
    const float* bdec  = (const float*)d_in[20];
    const float* Wfull = (const float*)d_in[21];
    // d_in[22] = bfull: softmax-shift-invariant, skipped.
    const float* Wg    = (const float*)d_in[23];
    const float* bg    = (const float*)d_in[24];
    const float* Wfc   = (const float*)d_in[25];
    const float* bfc   = (const float*)d_in[26];
    float* out = (float*)d_out;

    float *fh, *XpAll1, *XpAll2, *hidden, *att1, *att2, *alpha;
    float *bAll1, *bAll2, *fcH, *gate;
    uint32_t *featsP, *fhP, *x2P, *hidP, *aweP, *hstate;
    uint4 *Whh1p, *Whh1rp, *Whh2p, *Whh2rp;
    uint2 *WihAll1p, *WihAll2p, *Wencp, *Wdecp, *WfcHp, *WfcAp;
    cudaGetSymbolAddress((void**)&fh,      g_fh);
    cudaGetSymbolAddress((void**)&XpAll1,  g_XpAll1);
    cudaGetSymbolAddress((void**)&XpAll2,  g_XpAll2);
    cudaGetSymbolAddress((void**)&hidden,  g_hidden);
    cudaGetSymbolAddress((void**)&att1,    g_att1);
    cudaGetSymbolAddress((void**)&att2,    g_att2);
    cudaGetSymbolAddress((void**)&alpha,   g_alpha);
    cudaGetSymbolAddress((void**)&bAll1,   g_bAll1);
    cudaGetSymbolAddress((void**)&bAll2,   g_bAll2);
    cudaGetSymbolAddress((void**)&fcH,     g_fcH);
    cudaGetSymbolAddress((void**)&gate,    g_gate);
    cudaGetSymbolAddress((void**)&featsP,  g_featsP);
    cudaGetSymbolAddress((void**)&fhP,     g_fhP);
    cudaGetSymbolAddress((void**)&x2P,     g_x2P);
    cudaGetSymbolAddress((void**)&hidP,    g_hidP);
    cudaGetSymbolAddress((void**)&aweP,    g_aweP);
    cudaGetSymbolAddress((void**)&hstate,  g_hstate);
    cudaGetSymbolAddress((void**)&WihAll1p, g_WihAll1p);
    cudaGetSymbolAddress((void**)&WihAll2p, g_WihAll2p);
    cudaGetSymbolAddress((void**)&Whh1p,   g_Whh1p);
    cudaGetSymbolAddress((void**)&Whh1rp,  g_Whh1rp);
    cudaGetSymbolAddress((void**)&Whh2p,   g_Whh2p);
    cudaGetSymbolAddress((void**)&Whh2rp,  g_Whh2rp);
    cudaGetSymbolAddress((void**)&Wencp,   g_Wencp);
    cudaGetSymbolAddress((void**)&Wdecp,   g_Wdecp);
    cudaGetSymbolAddress((void**)&WfcHp,   g_WfcHp);
    cudaGetSymbolAddress((void**)&WfcAp,   g_WfcAp);

    const int off1h = (2048 / 8) * (512 / 16) * 32;
    const int off2h = (2048 / 8) * (1024 / 16) * 32;

    bool useSide = g_side.ok;
    cudaStream_t sd = useSide ? g_side.s : (cudaStream_t)0;

    if (useSide) {
        cudaEventRecord(g_side.fork, 0);
        cudaStreamWaitEvent(sd, g_side.fork, 0);
    }

    // ---- main stream: layer-1 path ----
    feats_kernel<<<(T_ * B_ * 256 + 255) / 256, 256>>>(enc, featsP);
    pack_wh<<<packGrid(2048, 512), 256>>>(Wih1,  WihAll1p,         2048, 512, 512, 0);
    pack_wh<<<packGrid(2048, 512), 256>>>(Wih1r, WihAll1p + off1h, 2048, 512, 512, 0);
    bias_combine<<<16, 256>>>(bih1, bhh1, bih1r, bhh1r, bAll1);
    pack_w<<<packGrid(2048, 512), 256>>>(Whh1,  Whh1p,  2048, 512);
    gemm_f16x2<<<dim3(64, 8), 256>>>(featsP, WihAll1p, bAll1,
                                     XpAll1, T_ * B_, 8 * D_, E_);
    pack_w<<<packGrid(2048, 512), 256>>>(Whh1r, Whh1rp, 2048, 512);
    lstm_persist<<<128, 256>>>(XpAll1, Whh1p, Whh1rp, hstate, x2P, nullptr);

    // ---- side stream (forked at entry) ----
    transpose_fh_kernel<<<dim3(16, 8, 64), dim3(32, 8), 0, sd>>>(enc, fh, fhP);
    pack_wh<<<packGrid(512, 512),   256, 0, sd>>>(Wenc, Wencp, 512, 512, 512, 0);
    gemm_f16x2<<<dim3(8, 128), 256, 0, sd>>>(fhP, Wencp, benc, att1, B_ * P_, A_, E_);
    pack_wh<<<packGrid(512, 1024),  256, 0, sd>>>(Wdec, Wdecp, 512, 1024, 1024, 0);
    pack_wh<<<packGrid(2048, 1024), 256, 0, sd>>>(Wih2,  WihAll2p,         2048, 1024, 1024, 0);
    pack_wh<<<packGrid(2048, 1024), 256, 0, sd>>>(Wih2r, WihAll2p + off2h, 2048, 1024, 1024, 0);
    pack_w<<<packGrid(2048, 512),  256, 0, sd>>>(Whh2,  Whh2p,  2048, 512);
    pack_w<<<packGrid(2048, 512),  256, 0, sd>>>(Whh2r, Whh2rp, 2048, 512);
    bias_combine<<<16, 256, 0, sd>>>(bih2, bhh2, bih2r, bhh2r, bAll2);
    pack_wh<<<packGrid(5000, 1024), 256, 0, sd>>>(Wfc, WfcHp, 5000, 1024, 1536, 0);
    pack_wh<<<packGrid(5000, 512),  256, 0, sd>>>(Wfc, WfcAp, 5000, 512, 1536, 1024);
    if (useSide) cudaEventRecord(g_side.join, sd);

    if (useSide) cudaStreamWaitEvent(0, g_side.join, 0);

    // ---- layer-2 ----
    gemm_f16x2<<<dim3(64, 8), 256>>>(x2P, WihAll2p, bAll2,
                                     XpAll2, T_ * B_, 8 * D_, 2 * D_);
    lstm_persist<<<128, 256>>>(XpAll2, Whh2p, Whh2rp, hstate, hidP, hidden);
    if (useSide) {
        cudaEventRecord(g_side.evL2, 0);
        cudaStreamWaitEvent(sd, g_side.evL2, 0);
    }

    // fcH = hidden @ WfcH.T (side stream, overlaps attention tail)
    gemm_f16x2<<<dim3((V_ + 63) / 64, 8), 256, 0, sd>>>(hidP, WfcHp, nullptr,
                                                        fcH, T_ * B_, V_, 2 * D_);
    if (useSide) cudaEventRecord(g_side.evFcH, sd);

    // ---- attention tail (main) ----
    gemm_f16x2<<<dim3(8, 8), 256>>>(hidP, Wdecp, bdec, att2, T_ * B_, A_, 2 * D_);
    att_softmax_kernel<<<T_ * B_, 256>>>(att1, att2, Wfull, alpha);
    awe_gate_kernel<<<B_, 512>>>(alpha, fh, hidden, Wg, bg, aweP, gate);
    if (useSide) cudaStreamWaitEvent(0, g_side.evFcH, 0);
    gemm_f16x2_fc<<<dim3((V_ + 63) / 64, 8), 256>>>(aweP, WfcAp, fcH, gate, bfc,
                                                    out, T_ * B_, V_, E_);
}

// round 17
// speedup vs baseline: 1.0422x; 1.0211x over previous
#include <cuda_runtime.h>
#include <cuda_bf16.h>
#include <cuda_fp16.h>
#include <math.h>
#include <stdint.h>

// ---------------------------------------------------------------------------
// DecoderWithAttention: B=64, E=512, H=W=16, T=16, D=512, A=512, V=5000
// Mixed-precision mma.sync pipeline (R16 + early evPk2 side-stream split):
//  - LSTM recurrence (Whh, h-state): bf16 hi/lo 3-pass (proven)
//  - Xp projections + attention + fc: fp16 hi/lo 2-pass (B hi-only)
//  - fc distributed + fused gate combine; gate fused into awe kernel
//  - side stream: layer-2 packs FIRST (evPk2 gates Xp2), then att1 path (join
//    gates att2), then fc packs (evFcH gates final GEMM).
// ---------------------------------------------------------------------------

#define B_ 64
#define E_ 512
#define T_ 16
#define D_ 512
#define P_ 256
#define A_ 512
#define V_ 5000

// ------------------------------ scratch ------------------------------------
__device__ float g_fh    [B_ * P_ * E_];
__device__ float g_XpAll1[T_ * B_ * 8 * D_];
__device__ float g_XpAll2[T_ * B_ * 8 * D_];
__device__ float g_hidden[T_ * B_ * 2 * D_];
__device__ float g_att1  [B_ * P_ * A_];
__device__ float g_att2  [T_ * B_ * A_];
__device__ float g_alpha [T_ * B_ * P_];
__device__ float g_bAll1 [8 * D_];
__device__ float g_bAll2 [8 * D_];
__device__ float g_fcH   [T_ * B_ * V_];
__device__ float g_gate  [T_ * B_ * 2];

// A-operand hi/lo planes (uint32 = 2 packed halves; lo plane at +M*K/2)
__device__ uint32_t g_featsP[2 * 1024 * 256];   // fp16 (Xp1)
__device__ uint32_t g_fhP  [2 * 16384 * 256];   // fp16 (att1)
__device__ uint32_t g_x2P  [2 * 1024 * 512];    // fp16 (Xp2)
__device__ uint32_t g_hidP [2 * 1024 * 512];    // fp16 (att2 + fcH)
__device__ uint32_t g_aweP [2 * 1024 * 256];    // fp16 (fcA)
__device__ uint32_t g_hstate[4 * 128 * 256];    // bf16 recurrence state

// bf16 fragment-packed weights (recurrence): [n8][k16][lane] uint4
__device__ uint4 g_Whh1p [(2048/8) * (512/16) * 32];
__device__ uint4 g_Whh1rp[(2048/8) * (512/16) * 32];
__device__ uint4 g_Whh2p [(2048/8) * (512/16) * 32];
__device__ uint4 g_Whh2rp[(2048/8) * (512/16) * 32];
// fp16 hi-only packed weights: [n8][k16][lane] uint2 {h0,h1}
__device__ uint2 g_WihAll1p[(4096/8) * (512/16)  * 32];
__device__ uint2 g_WihAll2p[(4096/8) * (1024/16) * 32];
__device__ uint2 g_Wencp [(512/8)  * (512/16) * 32];
__device__ uint2 g_Wdecp [(512/8)  * (1024/16)* 32];
__device__ uint2 g_WfcHp [(5000/8) * (1024/16)* 32];
__device__ uint2 g_WfcAp [(5000/8) * (512/16) * 32];

__device__ int g_bar_cnt = 0;
__device__ volatile int g_bar_sense = 0;

// ------------------------------ helpers ------------------------------------
__device__ __forceinline__ void mma_bf16(float* d, const uint32_t* a, const uint32_t* b) {
    asm volatile(
        "mma.sync.aligned.m16n8k16.row.col.f32.bf16.bf16.f32 "
        "{%0,%1,%2,%3}, {%4,%5,%6,%7}, {%8,%9}, {%0,%1,%2,%3};\n"
        : "+f"(d[0]), "+f"(d[1]), "+f"(d[2]), "+f"(d[3])
        : "r"(a[0]), "r"(a[1]), "r"(a[2]), "r"(a[3]), "r"(b[0]), "r"(b[1]));
}
__device__ __forceinline__ void mma_f16(float* d, const uint32_t* a, const uint32_t* b) {
    asm volatile(
        "mma.sync.aligned.m16n8k16.row.col.f32.f16.f16.f32 "
        "{%0,%1,%2,%3}, {%4,%5,%6,%7}, {%8,%9}, {%0,%1,%2,%3};\n"
        : "+f"(d[0]), "+f"(d[1]), "+f"(d[2]), "+f"(d[3])
        : "r"(a[0]), "r"(a[1]), "r"(a[2]), "r"(a[3]), "r"(b[0]), "r"(b[1]));
}

__device__ __forceinline__ void split2(float x0, float x1, uint32_t& hi, uint32_t& lo) {
    __nv_bfloat16 h0 = __float2bfloat16_rn(x0);
    __nv_bfloat16 h1 = __float2bfloat16_rn(x1);
    __nv_bfloat162 hp = __halves2bfloat162(h0, h1);
    hi = *(uint32_t*)&hp;
    __nv_bfloat162 lp = __floats2bfloat162_rn(x0 - __bfloat162float(h0),
                                              x1 - __bfloat162float(h1));
    lo = *(uint32_t*)&lp;
}
__device__ __forceinline__ void split2h(float x0, float x1, uint32_t& hi, uint32_t& lo) {
    __half h0 = __float2half_rn(x0);
    __half h1 = __float2half_rn(x1);
    __half2 hp = __halves2half2(h0, h1);
    hi = *(uint32_t*)&hp;
    __half2 lp = __floats2half2_rn(x0 - __half2float(h0), x1 - __half2float(h1));
    lo = *(uint32_t*)&lp;
}

// bf16 hi/lo fragment pack (recurrence weights)
__global__ void pack_w(const float* __restrict__ W, uint4* __restrict__ Wp,
                       int N, int K) {
    int idx = blockIdx.x * 256 + threadIdx.x;
    int K16 = K >> 4;
    int total = (N >> 3) * K16 * 32;
    if (idx >= total) return;
    int lane = idx & 31;
    int k16 = (idx >> 5) % K16;
    int n8 = idx / (32 * K16);
    int g = lane >> 2, tq = lane & 3;
    const float* src = W + (size_t)(n8 * 8 + g) * K + k16 * 16;
    uint4 o;
    split2(src[2 * tq],     src[2 * tq + 1], o.x, o.z);
    split2(src[2 * tq + 8], src[2 * tq + 9], o.y, o.w);
    Wp[idx] = o;
}

// fp16 hi-only fragment pack with source row-stride/column-offset
__global__ void pack_wh(const float* __restrict__ W, uint2* __restrict__ Wp,
                        int N, int K, int srcStride, int colOff) {
    int idx = blockIdx.x * 256 + threadIdx.x;
    int K16 = K >> 4;
    int total = (N >> 3) * K16 * 32;
    if (idx >= total) return;
    int lane = idx & 31;
    int k16 = (idx >> 5) % K16;
    int n8 = idx / (32 * K16);
    int g = lane >> 2, tq = lane & 3;
    const float* src = W + (size_t)(n8 * 8 + g) * srcStride + colOff + k16 * 16;
    __half2 a = __floats2half2_rn(src[2 * tq],     src[2 * tq + 1]);
    __half2 b = __floats2half2_rn(src[2 * tq + 8], src[2 * tq + 9]);
    Wp[idx] = make_uint2(*(uint32_t*)&a, *(uint32_t*)&b);
}

__global__ void bias_combine(const float* __restrict__ b1f, const float* __restrict__ b2f,
                             const float* __restrict__ b1r, const float* __restrict__ b2r,
                             float* __restrict__ out) {
    int i = blockIdx.x * 256 + threadIdx.x;
    if (i >= 8 * D_) return;
    out[i] = (i < 4 * D_) ? (b1f[i] + b2f[i]) : (b1r[i - 4 * D_] + b2r[i - 4 * D_]);
}

// fh[b][p][e] = enc[b][e][p]; emits fp32 fh + fp16 hi/lo planes
__global__ void transpose_fh_kernel(const float* __restrict__ enc, float* __restrict__ fh,
                                    uint32_t* __restrict__ fhP) {
    __shared__ float tile[32][33];
    const size_t FH_LO = (size_t)16384 * 256;
    int b  = blockIdx.z;
    int e0 = blockIdx.x * 32;
    int p0 = blockIdx.y * 32;
    int x = threadIdx.x;
#pragma unroll
    for (int i = 0; i < 4; i++) {
        int y = threadIdx.y + i * 8;
        tile[y][x] = enc[((size_t)b * E_ + e0 + y) * P_ + p0 + x];
    }
    __syncthreads();
    int it = threadIdx.y * 32 + threadIdx.x;
#pragma unroll
    for (int i = 0; i < 2; i++) {
        int item = it + i * 256;
        int yy = item >> 4;
        int xx = item & 15;
        float v0 = tile[2 * xx][yy];
        float v1 = tile[2 * xx + 1][yy];
        size_t row = (size_t)b * P_ + p0 + yy;
        fh[row * E_ + e0 + 2 * xx]     = v0;
        fh[row * E_ + e0 + 2 * xx + 1] = v1;
        uint32_t hw, lw;
        split2h(v0, v1, hw, lw);
        size_t w = row * 256 + (e0 >> 1) + xx;
        fhP[w] = hw;
        fhP[FH_LO + w] = lw;
    }
}

// feats fp16 planes
__global__ void feats_kernel(const float* __restrict__ enc, uint32_t* __restrict__ featsP) {
    const size_t F_LO = (size_t)1024 * 256;
    int gi = blockIdx.x * blockDim.x + threadIdx.x;
    if (gi >= T_ * B_ * 256) return;
    int t = gi & 15;
    int e2 = (gi >> 4) & 255;
    int b = gi >> 12;
    const float* s0 = enc + ((size_t)b * E_ + 2 * e2) * P_ + t;
    const float* s1 = s0 + P_;
    float a0 = 0.f, a1 = 0.f;
#pragma unroll
    for (int h = 0; h < 16; h++) { a0 += s0[h * 16]; a1 += s1[h * 16]; }
    uint32_t hw, lw;
    split2h(a0 * (1.f / 16.f), a1 * (1.f / 16.f), hw, lw);
    size_t w = ((size_t)t * B_ + b) * 256 + e2;
    featsP[w] = hw;
    featsP[F_LO + w] = lw;
}

#define ASW 12

// ---------------------- fp16x2 GEMM (2-pass, B hi-only) ----------------------
__global__ __launch_bounds__(256, 2) void gemm_f16x2(
    const uint32_t* __restrict__ Ap, const uint2* __restrict__ Wp,
    const float* __restrict__ b1,
    float* __restrict__ C, int M, int N, int K)
{
    __shared__ __align__(16) uint32_t Ah[2][128][ASW];
    __shared__ __align__(16) uint32_t Al[2][128][ASW];

    int tid  = threadIdx.x;
    int wid  = tid >> 5, lane = tid & 31;
    int g = lane >> 2, tq = lane & 3;
    int m0 = blockIdx.y * 128, n0 = blockIdx.x * 64;
    int wm = wid * 16;
    int K2 = K >> 1, K16 = K >> 4;
    int nTiles = N >> 3;
    size_t loOff = (size_t)M * K2;

    const uint2* bp[8];
    bool bok[8];
#pragma unroll
    for (int j = 0; j < 8; j++) {
        int n8 = (n0 >> 3) + j;
        bok[j] = (n8 < nTiles);
        bp[j] = Wp + ((size_t)(bok[j] ? n8 : 0) * K16) * 32 + lane;
    }

    float acc[8][4];
#pragma unroll
    for (int j = 0; j < 8; j++)
#pragma unroll
        for (int v = 0; v < 4; v++) acc[j][v] = 0.f;

    int r = tid >> 1, half = tid & 1;
    const uint4* aH = (const uint4*)(Ap + (size_t)(m0 + r) * K2) + half;
    const uint4* aL = (const uint4*)(Ap + loOff + (size_t)(m0 + r) * K2) + half;

    {
        uint4 h = aH[0], l = aL[0];
        *(uint4*)&Ah[0][r][half * 4] = h;
        *(uint4*)&Al[0][r][half * 4] = l;
    }
    __syncthreads();

    int buf = 0;
    for (int kt = 0; kt < K16; kt++) {
        bool more = (kt + 1) < K16;
        uint4 nh, nl;
        if (more) {
            nh = aH[(kt + 1) * 2];
            nl = aL[(kt + 1) * 2];
        }
        uint32_t ah[4], al[4];
        {
            int rA = wm + g, rB = rA + 8;
            ah[0] = Ah[buf][rA][tq];     ah[1] = Ah[buf][rB][tq];
            ah[2] = Ah[buf][rA][tq + 4]; ah[3] = Ah[buf][rB][tq + 4];
            al[0] = Al[buf][rA][tq];     al[1] = Al[buf][rB][tq];
            al[2] = Al[buf][rA][tq + 4]; al[3] = Al[buf][rB][tq + 4];
        }
#pragma unroll
        for (int j = 0; j < 8; j++) {
            uint2 bv = bok[j] ? bp[j][kt * 32] : make_uint2(0u, 0u);
            uint32_t bh[2] = {bv.x, bv.y};
            mma_f16(acc[j], ah, bh);
            mma_f16(acc[j], al, bh);
        }
        if (more) {
            *(uint4*)&Ah[buf ^ 1][r][half * 4] = nh;
            *(uint4*)&Al[buf ^ 1][r][half * 4] = nl;
            __syncthreads();
            buf ^= 1;
        }
    }

#pragma unroll
    for (int j = 0; j < 8; j++) {
        int rr = m0 + wm + g;
        int c0 = n0 + j * 8 + 2 * tq;
#pragma unroll
        for (int cc = 0; cc < 2; cc++) {
            int c = c0 + cc;
            if (c < N) {
                float bias = b1 ? b1[c] : 0.f;
                C[(size_t)rr * N + c]       = acc[j][cc]     + bias;
                C[(size_t)(rr + 8) * N + c] = acc[j][2 + cc] + bias;
            }
        }
    }
}

// ------------- fp16x2 GEMM with fused gate-combine epilogue ------------------
// out[r][c] = g0[r]*fcH[r][c] + g1[r]*acc[r][c] + bfc[c]
__global__ __launch_bounds__(256, 2) void gemm_f16x2_fc(
    const uint32_t* __restrict__ Ap, const uint2* __restrict__ Wp,
    const float* __restrict__ fcH, const float* __restrict__ gate,
    const float* __restrict__ bfc,
    float* __restrict__ C, int M, int N, int K)
{
    __shared__ __align__(16) uint32_t Ah[2][128][ASW];
    __shared__ __align__(16) uint32_t Al[2][128][ASW];

    int tid  = threadIdx.x;
    int wid  = tid >> 5, lane = tid & 31;
    int g = lane >> 2, tq = lane & 3;
    int m0 = blockIdx.y * 128, n0 = blockIdx.x * 64;
    int wm = wid * 16;
    int K2 = K >> 1, K16 = K >> 4;
    int nTiles = N >> 3;
    size_t loOff = (size_t)M * K2;

    const uint2* bp[8];
    bool bok[8];
#pragma unroll
    for (int j = 0; j < 8; j++) {
        int n8 = (n0 >> 3) + j;
        bok[j] = (n8 < nTiles);
        bp[j] = Wp + ((size_t)(bok[j] ? n8 : 0) * K16) * 32 + lane;
    }

    float acc[8][4];
#pragma unroll
    for (int j = 0; j < 8; j++)
#pragma unroll
        for (int v = 0; v < 4; v++) acc[j][v] = 0.f;

    int r = tid >> 1, half = tid & 1;
    const uint4* aH = (const uint4*)(Ap + (size_t)(m0 + r) * K2) + half;
    const uint4* aL = (const uint4*)(Ap + loOff + (size_t)(m0 + r) * K2) + half;

    {
        uint4 h = aH[0], l = aL[0];
        *(uint4*)&Ah[0][r][half * 4] = h;
        *(uint4*)&Al[0][r][half * 4] = l;
    }
    __syncthreads();

    int buf = 0;
    for (int kt = 0; kt < K16; kt++) {
        bool more = (kt + 1) < K16;
        uint4 nh, nl;
        if (more) {
            nh = aH[(kt + 1) * 2];
            nl = aL[(kt + 1) * 2];
        }
        uint32_t ah[4], al[4];
        {
            int rA = wm + g, rB = rA + 8;
            ah[0] = Ah[buf][rA][tq];     ah[1] = Ah[buf][rB][tq];
            ah[2] = Ah[buf][rA][tq + 4]; ah[3] = Ah[buf][rB][tq + 4];
            al[0] = Al[buf][rA][tq];     al[1] = Al[buf][rB][tq];
            al[2] = Al[buf][rA][tq + 4]; al[3] = Al[buf][rB][tq + 4];
        }
#pragma unroll
        for (int j = 0; j < 8; j++) {
            uint2 bv = bok[j] ? bp[j][kt * 32] : make_uint2(0u, 0u);
            uint32_t bh[2] = {bv.x, bv.y};
            mma_f16(acc[j], ah, bh);
            mma_f16(acc[j], al, bh);
        }
        if (more) {
            *(uint4*)&Ah[buf ^ 1][r][half * 4] = nh;
            *(uint4*)&Al[buf ^ 1][r][half * 4] = nl;
            __syncthreads();
            buf ^= 1;
        }
    }

    int rr0 = m0 + wm + g;
    float g0a = gate[(size_t)rr0 * 2],       g1a = gate[(size_t)rr0 * 2 + 1];
    float g0b = gate[(size_t)(rr0 + 8) * 2], g1b = gate[(size_t)(rr0 + 8) * 2 + 1];
#pragma unroll
    for (int j = 0; j < 8; j++) {
        int c0 = n0 + j * 8 + 2 * tq;
#pragma unroll
        for (int cc = 0; cc < 2; cc++) {
            int c = c0 + cc;
            if (c < N) {
                float bias = bfc[c];
                size_t ia = (size_t)rr0 * N + c;
                size_t ib = (size_t)(rr0 + 8) * N + c;
                C[ia] = g0a * fcH[ia] + g1a * acc[j][cc]     + bias;
                C[ib] = g0b * fcH[ib] + g1b * acc[j][2 + cc] + bias;
            }
        }
    }
}

// ---------------------- persistent LSTM (split-K, bf16 3-pass) ---------------
__device__ __forceinline__ void grid_barrier(int step) {
    __threadfence();
    __syncthreads();
    if (threadIdx.x == 0) {
        int target = (step + 1) & 1;
        if (atomicAdd(&g_bar_cnt, 1) == (int)gridDim.x - 1) {
            atomicExch(&g_bar_cnt, 0);
            __threadfence();
            g_bar_sense = target;
        } else {
            while (g_bar_sense != target) __nanosleep(32);
        }
        __threadfence();
    }
    __syncthreads();
}

// 128 blocks x 256 threads. dir = bid>>6, d-slice = bid&63 (8 d each).
__global__ __launch_bounds__(256) void lstm_persist(
    const float* __restrict__ XpAll,
    const uint4* __restrict__ Whfp, const uint4* __restrict__ Whrp,
    uint32_t* __restrict__ hstate,
    uint32_t* __restrict__ outP, float* __restrict__ outF32)
{
    __shared__ __align__(16) uint32_t Hh[2][128][ASW];
    __shared__ __align__(16) uint32_t Hl[2][128][ASW];
    __shared__ float red[4][32][16];

    const int HS = 128 * 256;
    const size_t OUT_LO = (size_t)1024 * 512;

    int tid = threadIdx.x;
    int w = tid >> 5, lane = tid & 31;
    int g = lane >> 2, tq = lane & 3;
    int dir = blockIdx.x >> 6;
    int idx = blockIdx.x & 63;
    int d0 = idx * 8;
    const uint4* Whp = dir ? Whrp : Whfp;
    const int K16tot = D_ >> 4;
    int kg = w >> 2;
    int wl = w & 3;

    const uint4* bp[4];
#pragma unroll
    for (int j = 0; j < 4; j++)
        bp[j] = Whp + ((size_t)(j * 64 + idx) * K16tot) * 32 + lane;

    int sKg = tid >> 7;
    int sR  = (tid >> 1) & 63;
    int sKh = tid & 1;

    float creg[4] = {0.f, 0.f, 0.f, 0.f};

    for (int t = 0; t < T_; t++) {
        float acc[4][4];
#pragma unroll
        for (int j = 0; j < 4; j++)
#pragma unroll
            for (int v = 0; v < 4; v++) acc[j][v] = 0.f;

        if (t > 0) {
            int ib = (t - 1) & 1;
            const uint32_t* hHi = hstate + (size_t)(2 * ib) * HS;
            const uint32_t* hLo = hHi + HS;
            const uint4* sH = (const uint4*)(hHi + (size_t)(dir * 64 + sR) * 256) + sKg * 32 + sKh;
            const uint4* sL = (const uint4*)(hLo + (size_t)(dir * 64 + sR) * 256) + sKg * 32 + sKh;

            {
                uint4 h = sH[0], l = sL[0];
                *(uint4*)&Hh[0][sKg * 64 + sR][sKh * 4] = h;
                *(uint4*)&Hl[0][sKg * 64 + sR][sKh * 4] = l;
            }
            uint4 breg[4];
#pragma unroll
            for (int j = 0; j < 4; j++) breg[j] = bp[j][(kg * 16) * 32];
            __syncthreads();

            int buf = 0;
            for (int kt = 0; kt < 16; kt++) {
                bool more = (kt + 1) < 16;
                uint4 nh, nl, bnext[4];
                if (more) {
                    nh = sH[(kt + 1) * 2];
                    nl = sL[(kt + 1) * 2];
#pragma unroll
                    for (int j = 0; j < 4; j++) bnext[j] = bp[j][(kg * 16 + kt + 1) * 32];
                }
                int rA = kg * 64 + wl * 16 + g, rB = rA + 8;
                uint32_t ah[4], al[4];
                ah[0] = Hh[buf][rA][tq];     ah[1] = Hh[buf][rB][tq];
                ah[2] = Hh[buf][rA][tq + 4]; ah[3] = Hh[buf][rB][tq + 4];
                al[0] = Hl[buf][rA][tq];     al[1] = Hl[buf][rB][tq];
                al[2] = Hl[buf][rA][tq + 4]; al[3] = Hl[buf][rB][tq + 4];
#pragma unroll
                for (int j = 0; j < 4; j++) {
                    uint32_t bh[2] = {breg[j].x, breg[j].y};
                    uint32_t bl[2] = {breg[j].z, breg[j].w};
                    mma_bf16(acc[j], ah, bh);
                    mma_bf16(acc[j], al, bh);
                    mma_bf16(acc[j], ah, bl);
                }
                if (more) {
                    *(uint4*)&Hh[buf ^ 1][sKg * 64 + sR][sKh * 4] = nh;
                    *(uint4*)&Hl[buf ^ 1][sKg * 64 + sR][sKh * 4] = nl;
                    __syncthreads();
                    buf ^= 1;
#pragma unroll
                    for (int j = 0; j < 4; j++) breg[j] = bnext[j];
                }
            }
            if (w >= 4) {
#pragma unroll
                for (int j = 0; j < 4; j++)
#pragma unroll
                    for (int v = 0; v < 4; v++) red[wl][lane][j * 4 + v] = acc[j][v];
            }
            __syncthreads();
            if (w < 4) {
#pragma unroll
                for (int j = 0; j < 4; j++)
#pragma unroll
                    for (int v = 0; v < 4; v++) acc[j][v] += red[w][lane][j * 4 + v];
            }
        }

        if (w < 4) {
            int ob = t & 1;
            uint32_t* oHi = hstate + (size_t)(2 * ob) * HS;
            uint32_t* oLo = oHi + HS;
#pragma unroll
            for (int rr = 0; rr < 2; rr++) {
                int rb = w * 16 + g + rr * 8;
                size_t trow = (dir == 0) ? ((size_t)t * B_ + rb)
                                         : ((size_t)(15 - t) * B_ + rb);
                const float* xp = XpAll + trow * (8 * D_) + (dir ? 4 * D_ : 0);
                float hvv[2];
#pragma unroll
                for (int cc = 0; cc < 2; cc++) {
                    int d  = d0 + 2 * tq + cc;
                    int vi = rr * 2 + cc;
                    float iv = acc[0][vi] + xp[0 * D_ + d];
                    float fv = acc[1][vi] + xp[1 * D_ + d];
                    float gv = acc[2][vi] + xp[2 * D_ + d];
                    float ov = acc[3][vi] + xp[3 * D_ + d];
                    float co = creg[vi];
                    float si = 1.f / (1.f + expf(-iv));
                    float sf = 1.f / (1.f + expf(-fv));
                    float so = 1.f / (1.f + expf(-ov));
                    float cn = sf * co + si * tanhf(gv);
                    float hv = so * tanhf(cn);
                    creg[vi] = cn;
                    hvv[cc] = hv;
                    if (outF32)
                        outF32[trow * (2 * D_) + D_ * dir + d] = hv;
                }
                uint32_t hw, lw;
                split2(hvv[0], hvv[1], hw, lw);
                int word = (d0 >> 1) + tq;
                oHi[(size_t)(dir * 64 + rb) * 256 + word] = hw;
                oLo[(size_t)(dir * 64 + rb) * 256 + word] = lw;
                uint32_t ohw, olw;
                split2h(hvv[0], hvv[1], ohw, olw);
                size_t ow = trow * 512 + 256 * dir + word;
                outP[ow] = ohw;
                outP[OUT_LO + ow] = olw;
            }
        }
        grid_barrier(t);
    }
}

// ------------------------- attention score + softmax -------------------------
__global__ __launch_bounds__(256) void att_softmax_kernel(
    const float* __restrict__ att1, const float* __restrict__ att2,
    const float* __restrict__ Wfull, float* __restrict__ alpha)
{
    __shared__ float a2s[A_];
    __shared__ float wfl[A_];
    __shared__ float attv[P_];
    __shared__ float red[256];

    int tid = threadIdx.x;
    int t = blockIdx.x >> 6;
    int b = blockIdx.x & 63;

    const float* a2 = att2 + ((size_t)t * B_ + b) * A_;
#pragma unroll
    for (int i = 0; i < 2; i++) {
        int a = tid + i * 256;
        a2s[a] = a2[a];
        wfl[a] = Wfull[a];
    }
    __syncthreads();

    int warp = tid >> 5, lane = tid & 31;
    for (int p = warp; p < P_; p += 8) {
        const float* a1 = att1 + ((size_t)b * P_ + p) * A_;
        float s = 0.f;
        for (int a = lane; a < A_; a += 32) {
            float v = a1[a] + a2s[a];
            s += fmaxf(v, 0.f) * wfl[a];
        }
#pragma unroll
        for (int off = 16; off; off >>= 1) s += __shfl_xor_sync(0xffffffffu, s, off);
        if (lane == 0) attv[p] = s;
    }
    __syncthreads();

    float x = attv[tid];
    red[tid] = x;
    __syncthreads();
    for (int s = 128; s; s >>= 1) {
        if (tid < s) red[tid] = fmaxf(red[tid], red[tid + s]);
        __syncthreads();
    }
    float mx = red[0];
    __syncthreads();
    float e = expf(x - mx);
    red[tid] = e;
    __syncthreads();
    for (int s = 128; s; s >>= 1) {
        if (tid < s) red[tid] += red[tid + s];
        __syncthreads();
    }
    float sum = red[0];
    alpha[((size_t)t * B_ + b) * P_ + tid] = e / sum;
}

// awe + gate fused: aweP fp16 planes + gate scalars (per b block, 512 thr)
__global__ __launch_bounds__(512) void awe_gate_kernel(
    const float* __restrict__ alpha, const float* __restrict__ fh,
    const float* __restrict__ hidden,
    const float* __restrict__ Wg, const float* __restrict__ bg,
    uint32_t* __restrict__ aweP, float* __restrict__ gate)
{
    __shared__ float al[T_][P_];
    __shared__ float gred[16][T_][2];
    const size_t AW_LO = (size_t)1024 * 256;
    const int F = 2 * D_ + E_;
    int b = blockIdx.x;
    int tid = threadIdx.x;
    int wid = tid >> 5, lane = tid & 31;
#pragma unroll
    for (int i = 0; i < 8; i++) {
        int idx = tid + i * 512;
        int t = idx >> 8, p = idx & 255;
        al[t][p] = alpha[((size_t)t * B_ + b) * P_ + p];
    }
    __syncthreads();
    float acc[T_];
#pragma unroll
    for (int t = 0; t < T_; t++) acc[t] = 0.f;
    const float* fhb = fh + (size_t)b * P_ * E_;
    for (int p = 0; p < P_; p++) {
        float v = fhb[(size_t)p * E_ + tid];
#pragma unroll
        for (int t = 0; t < T_; t++) acc[t] += al[t][p] * v;
    }
    float wa0 = Wg[1024 + tid], wa1 = Wg[F + 1024 + tid];
    float wh00 = Wg[tid], wh01 = Wg[tid + 512];
    float wh10 = Wg[F + tid], wh11 = Wg[F + tid + 512];
#pragma unroll
    for (int t = 0; t < T_; t++) {
        size_t trow = (size_t)t * B_ + b;
        float other = __shfl_xor_sync(0xffffffffu, acc[t], 1);
        if ((tid & 1) == 0) {
            uint32_t hw, lw;
            split2h(acc[t], other, hw, lw);
            aweP[trow * 256 + (tid >> 1)] = hw;
            aweP[AW_LO + trow * 256 + (tid >> 1)] = lw;
        }
        float hv0 = hidden[trow * (2 * D_) + tid];
        float hv1 = hidden[trow * (2 * D_) + tid + 512];
        float p0 = acc[t] * wa0 + hv0 * wh00 + hv1 * wh01;
        float p1 = acc[t] * wa1 + hv0 * wh10 + hv1 * wh11;
#pragma unroll
        for (int off = 16; off; off >>= 1) {
            p0 += __shfl_xor_sync(0xffffffffu, p0, off);
            p1 += __shfl_xor_sync(0xffffffffu, p1, off);
        }
        if (lane == 0) { gred[wid][t][0] = p0; gred[wid][t][1] = p1; }
    }
    __syncthreads();
    if (tid < T_) {
        float z0 = 0.f, z1 = 0.f;
#pragma unroll
        for (int w = 0; w < 16; w++) { z0 += gred[w][tid][0]; z1 += gred[w][tid][1]; }
        z0 += bg[0]; z1 += bg[1];
        float g0 = 1.f / (1.f + expf(z1 - z0));
        size_t row = (size_t)tid * B_ + b;
        gate[row * 2]     = g0;
        gate[row * 2 + 1] = 1.f - g0;
    }
}

// ------------------------------ side-stream infra ----------------------------
namespace {
struct SideInfra {
    cudaStream_t s = nullptr;
    cudaEvent_t fork = nullptr, evPk2 = nullptr, join = nullptr, evL2 = nullptr, evFcH = nullptr;
    bool ok = false;
    SideInfra() {
        if (cudaStreamCreateWithFlags(&s, cudaStreamNonBlocking) != cudaSuccess) return;
        if (cudaEventCreateWithFlags(&fork, cudaEventDisableTiming) != cudaSuccess) return;
        if (cudaEventCreateWithFlags(&evPk2, cudaEventDisableTiming) != cudaSuccess) return;
        if (cudaEventCreateWithFlags(&join, cudaEventDisableTiming) != cudaSuccess) return;
        if (cudaEventCreateWithFlags(&evL2, cudaEventDisableTiming) != cudaSuccess) return;
        if (cudaEventCreateWithFlags(&evFcH, cudaEventDisableTiming) != cudaSuccess) return;
        ok = true;
    }
};
SideInfra g_side;
}

// ------------------------------ launcher ------------------------------------
static inline int packGrid(int N, int K) { return ((N / 8) * (K / 16) * 32 + 255) / 256; }

extern "C" void kernel_launch(void* const* d_in, const int* in_sizes, int n_in,
                              void* d_out, int out_size)
{
    const float* enc   = (const float*)d_in[0];
    const float* Wih1  = (const float*)d_in[1];
    const float* Whh1  = (const float*)d_in[2];
    const float* bih1  = (const float*)d_in[3];
    const float* bhh1  = (const float*)d_in[4];
    const float* Wih1r = (const float*)d_in[5];
    const float* Whh1r = (const float*)d_in[6];
    const float* bih1r = (const float*)d_in[7];
    const float* bhh1r = (const float*)d_in[8];
    const float* Wih2  = (const float*)d_in[9];
    const float* Whh2  = (const float*)d_in[10];
    const float* bih2  = (const float*)d_in[11];
    const float* bhh2  = (const float*)d_in[12];
    const float* Wih2r = (const float*)d_in[13];
    const float* Whh2r = (const float*)d_in[14];
    const float* bih2r = (const float*)d_in[15];
    const float* bhh2r = (const float*)d_in[16];
    const float* Wenc  = (const float*)d_in[17];
    const float* benc  = (const float*)d_in[18];
    const float* Wdec  = (const float*)d_in[19];
    const float* bdec  = (const float*)d_in[20];
    const float* Wfull = (const float*)d_in[21];
    // d_in[22] = bfull: softmax-shift-invariant, skipped.
    const float* Wg    = (const float*)d_in[23];
    const float* bg    = (const float*)d_in[24];
    const float* Wfc   = (const float*)d_in[25];
    const float* bfc   = (const float*)d_in[26];
    float* out = (float*)d_out;

    float *fh, *XpAll1, *XpAll2, *hidden, *att1, *att2, *alpha;
    float *bAll1, *bAll2, *fcH, *gate;
    uint32_t *featsP, *fhP, *x2P, *hidP, *aweP, *hstate;
    uint4 *Whh1p, *Whh1rp, *Whh2p, *Whh2rp;
    uint2 *WihAll1p, *WihAll2p, *Wencp, *Wdecp, *WfcHp, *WfcAp;
    cudaGetSymbolAddress((void**)&fh,      g_fh);
    cudaGetSymbolAddress((void**)&XpAll1,  g_XpAll1);
    cudaGetSymbolAddress((void**)&XpAll2,  g_XpAll2);
    cudaGetSymbolAddress((void**)&hidden,  g_hidden);
    cudaGetSymbolAddress((void**)&att1,    g_att1);
    cudaGetSymbolAddress((void**)&att2,    g_att2);
    cudaGetSymbolAddress((void**)&alpha,   g_alpha);
    cudaGetSymbolAddress((void**)&bAll1,   g_bAll1);
    cudaGetSymbolAddress((void**)&bAll2,   g_bAll2);
    cudaGetSymbolAddress((void**)&fcH,     g_fcH);
    cudaGetSymbolAddress((void**)&gate,    g_gate);
    cudaGetSymbolAddress((void**)&featsP,  g_featsP);
    cudaGetSymbolAddress((void**)&fhP,     g_fhP);
    cudaGetSymbolAddress((void**)&x2P,     g_x2P);
    cudaGetSymbolAddress((void**)&hidP,    g_hidP);
    cudaGetSymbolAddress((void**)&aweP,    g_aweP);
    cudaGetSymbolAddress((void**)&hstate,  g_hstate);
    cudaGetSymbolAddress((void**)&WihAll1p, g_WihAll1p);
    cudaGetSymbolAddress((void**)&WihAll2p, g_WihAll2p);
    cudaGetSymbolAddress((void**)&Whh1p,   g_Whh1p);
    cudaGetSymbolAddress((void**)&Whh1rp,  g_Whh1rp);
    cudaGetSymbolAddress((void**)&Whh2p,   g_Whh2p);
    cudaGetSymbolAddress((void**)&Whh2rp,  g_Whh2rp);
    cudaGetSymbolAddress((void**)&Wencp,   g_Wencp);
    cudaGetSymbolAddress((void**)&Wdecp,   g_Wdecp);
    cudaGetSymbolAddress((void**)&WfcHp,   g_WfcHp);
    cudaGetSymbolAddress((void**)&WfcAp,   g_WfcAp);

    const int off1h = (2048 / 8) * (512 / 16) * 32;
    const int off2h = (2048 / 8) * (1024 / 16) * 32;

    bool useSide = g_side.ok;
    cudaStream_t sd = useSide ? g_side.s : (cudaStream_t)0;

    if (useSide) {
        cudaEventRecord(g_side.fork, 0);
        cudaStreamWaitEvent(sd, g_side.fork, 0);
    }

    // ---- main stream: layer-1 path ----
    feats_kernel<<<(T_ * B_ * 256 + 255) / 256, 256>>>(enc, featsP);
    pack_wh<<<packGrid(2048, 512), 256>>>(Wih1,  WihAll1p,         2048, 512, 512, 0);
    pack_wh<<<packGrid(2048, 512), 256>>>(Wih1r, WihAll1p + off1h, 2048, 512, 512, 0);
    bias_combine<<<16, 256>>>(bih1, bhh1, bih1r, bhh1r, bAll1);
    pack_w<<<packGrid(2048, 512), 256>>>(Whh1,  Whh1p,  2048, 512);
    gemm_f16x2<<<dim3(64, 8), 256>>>(featsP, WihAll1p, bAll1,
                                     XpAll1, T_ * B_, 8 * D_, E_);
    pack_w<<<packGrid(2048, 512), 256>>>(Whh1r, Whh1rp, 2048, 512);
    lstm_persist<<<128, 256>>>(XpAll1, Whh1p, Whh1rp, hstate, x2P, nullptr);

    // ---- side stream (forked at entry): layer-2 prerequisites FIRST ----
    pack_wh<<<packGrid(2048, 1024), 256, 0, sd>>>(Wih2,  WihAll2p,         2048, 1024, 1024, 0);
    pack_wh<<<packGrid(2048, 1024), 256, 0, sd>>>(Wih2r, WihAll2p + off2h, 2048, 1024, 1024, 0);
    pack_w<<<packGrid(2048, 512),  256, 0, sd>>>(Whh2,  Whh2p,  2048, 512);
    pack_w<<<packGrid(2048, 512),  256, 0, sd>>>(Whh2r, Whh2rp, 2048, 512);
    bias_combine<<<16, 256, 0, sd>>>(bih2, bhh2, bih2r, bhh2r, bAll2);
    if (useSide) cudaEventRecord(g_side.evPk2, sd);

    // ---- side stream: att1 path ----
    transpose_fh_kernel<<<dim3(16, 8, 64), dim3(32, 8), 0, sd>>>(enc, fh, fhP);
    pack_wh<<<packGrid(512, 512),  256, 0, sd>>>(Wenc, Wencp, 512, 512, 512, 0);
    gemm_f16x2<<<dim3(8, 128), 256, 0, sd>>>(fhP, Wencp, benc, att1, B_ * P_, A_, E_);
    pack_wh<<<packGrid(512, 1024), 256, 0, sd>>>(Wdec, Wdecp, 512, 1024, 1024, 0);
    if (useSide) cudaEventRecord(g_side.join, sd);

    // ---- side stream: fc packs ----
    pack_wh<<<packGrid(5000, 1024), 256, 0, sd>>>(Wfc, WfcHp, 5000, 1024, 1536, 0);
    pack_wh<<<packGrid(5000, 512),  256, 0, sd>>>(Wfc, WfcAp, 5000, 512, 1536, 1024);

    // ---- layer-2 (gated only on evPk2 + lstm1) ----
    if (useSide) cudaStreamWaitEvent(0, g_side.evPk2, 0);
    gemm_f16x2<<<dim3(64, 8), 256>>>(x2P, WihAll2p, bAll2,
                                     XpAll2, T_ * B_, 8 * D_, 2 * D_);
    lstm_persist<<<128, 256>>>(XpAll2, Whh2p, Whh2rp, hstate, hidP, hidden);
    if (useSide) {
        cudaEventRecord(g_side.evL2, 0);
        cudaStreamWaitEvent(sd, g_side.evL2, 0);
    }

    // fcH = hidden @ WfcH.T (side stream, overlaps attention tail)
    gemm_f16x2<<<dim3((V_ + 63) / 64, 8), 256, 0, sd>>>(hidP, WfcHp, nullptr,
                                                        fcH, T_ * B_, V_, 2 * D_);
    if (useSide) cudaEventRecord(g_side.evFcH, sd);

    // ---- attention tail (main; att2 needs att1+Wdecp via join) ----
    if (useSide) cudaStreamWaitEvent(0, g_side.join, 0);
    gemm_f16x2<<<dim3(8, 8), 256>>>(hidP, Wdecp, bdec, att2, T_ * B_, A_, 2 * D_);
    att_softmax_kernel<<<T_ * B_, 256>>>(att1, att2, Wfull, alpha);
    awe_gate_kernel<<<B_, 512>>>(alpha, fh, hidden, Wg, bg, aweP, gate);
    if (useSide) cudaStreamWaitEvent(0, g_side.evFcH, 0);
    gemm_f16x2_fc<<<dim3((V_ + 63) / 64, 8), 256>>>(aweP, WfcAp, fcH, gate, bfc,
                                                    out, T_ * B_, V_, E_);
}